// round 9
// baseline (speedup 1.0000x reference)
#include <cuda_runtime.h>
#include <cuda_bf16.h>
#include <stdint.h>
#include <math.h>

#define N_NODES 256
#define F_IN    128
#define F_OUT   64
#define BT_TOTAL 512
#define NTHR    512

// bf16 row pitch 72 elems (144B): 144 mod 128 = 16 -> conflict-free ldmatrix
#define PITCH   72

// ---- smem byte offsets ----
#define AB_SIZE  (128 * PITCH * 2)          // 18432 B per hi/lo block (A chunk [128m][64k])
#define R_AB     0                          // 4 blocks: (buf*2 + hl)*AB_SIZE = 73728
#define R_W_HI   73728                      // W [128][72] bf16
#define R_W_LO   92160
#define R_B2_HI  110592                     // Wh [256][72] bf16
#define R_B2_LO  147456
#define R_WH1    184320                     // [256] f32
#define R_WH2    185344                     // [256] f32
#define R_ST4    186368                     // [256] float4 (wh1, rmax, rinv, _)
#define R_AV     190464                     // a vector [128] f32
#define SM_TOTAL 190976

#define BFULL(b)  (1 + (b))
#define BEMPTY(b) (3 + (b))

static __device__ __forceinline__ void bar_sync_id(int id) {
    asm volatile("bar.sync %0, %1;" :: "r"(id), "r"(NTHR) : "memory");
}
static __device__ __forceinline__ void bar_arrive_id(int id) {
    asm volatile("bar.arrive %0, %1;" :: "r"(id), "r"(NTHR) : "memory");
}
static __device__ __forceinline__ uint32_t smem_u32(const void* p) {
    uint32_t a;
    asm("{ .reg .u64 t; cvta.to.shared.u64 t, %1; cvt.u32.u64 %0, t; }" : "=r"(a) : "l"(p));
    return a;
}
static __device__ __forceinline__ void ldsm4(uint32_t& r0, uint32_t& r1, uint32_t& r2, uint32_t& r3, uint32_t addr) {
    asm volatile("ldmatrix.sync.aligned.m8n8.x4.shared.b16 {%0,%1,%2,%3}, [%4];"
                 : "=r"(r0), "=r"(r1), "=r"(r2), "=r"(r3) : "r"(addr));
}
static __device__ __forceinline__ void ldsm4t(uint32_t& r0, uint32_t& r1, uint32_t& r2, uint32_t& r3, uint32_t addr) {
    asm volatile("ldmatrix.sync.aligned.m8n8.x4.trans.shared.b16 {%0,%1,%2,%3}, [%4];"
                 : "=r"(r0), "=r"(r1), "=r"(r2), "=r"(r3) : "r"(addr));
}
static __device__ __forceinline__ void mma16816(float* c,
        uint32_t a0, uint32_t a1, uint32_t a2, uint32_t a3, uint32_t b0, uint32_t b1) {
    asm volatile("mma.sync.aligned.m16n8k16.row.col.f32.bf16.bf16.f32 "
                 "{%0,%1,%2,%3}, {%4,%5,%6,%7}, {%8,%9}, {%0,%1,%2,%3};"
                 : "+f"(c[0]), "+f"(c[1]), "+f"(c[2]), "+f"(c[3])
                 : "r"(a0), "r"(a1), "r"(a2), "r"(a3), "r"(b0), "r"(b1));
}
// packed split: hi word = {bf16(y), bf16(x)}, lo word = residuals
static __device__ __forceinline__ void split2(float x, float y, uint32_t& hi, uint32_t& lo) {
    asm("cvt.rn.bf16x2.f32 %0, %1, %2;" : "=r"(hi) : "f"(y), "f"(x));
    float rx = __uint_as_float(hi << 16);
    float ry = __uint_as_float(hi & 0xFFFF0000u);
    asm("cvt.rn.bf16x2.f32 %0, %1, %2;" : "=r"(lo) : "f"(y - ry), "f"(x - rx));
}
static __device__ __forceinline__ void split4(float4 v, uint2& hi, uint2& lo) {
    split2(v.x, v.y, hi.x, lo.x);
    split2(v.z, v.w, hi.y, lo.y);
}

// 4-kstep (64 k) warp GEMM chunk on a 16m x 32n tile, 3-term bf16 split,
// double-buffered fragments.
static __device__ __forceinline__ void gemm_chunk(float acc[4][4],
        uint32_t aHi, uint32_t aLo, uint32_t bHi, uint32_t bLo)
{
    uint32_t ah[2][4], al[2][4], bh[2][8], bl[2][8];
    ldsm4(ah[0][0], ah[0][1], ah[0][2], ah[0][3], aHi);
    ldsm4(al[0][0], al[0][1], al[0][2], al[0][3], aLo);
    ldsm4t(bh[0][0], bh[0][1], bh[0][2], bh[0][3], bHi);
    ldsm4t(bh[0][4], bh[0][5], bh[0][6], bh[0][7], bHi + 32);
    ldsm4t(bl[0][0], bl[0][1], bl[0][2], bl[0][3], bLo);
    ldsm4t(bl[0][4], bl[0][5], bl[0][6], bl[0][7], bLo + 32);
    #pragma unroll
    for (int k0 = 0; k0 < 4; ++k0) {
        const int cur = k0 & 1, nxt = cur ^ 1;
        if (k0 < 3) {
            const int ka = (k0 + 1) * 32;
            const int kb = (k0 + 1) * 16 * (PITCH * 2);
            ldsm4(ah[nxt][0], ah[nxt][1], ah[nxt][2], ah[nxt][3], aHi + ka);
            ldsm4(al[nxt][0], al[nxt][1], al[nxt][2], al[nxt][3], aLo + ka);
            ldsm4t(bh[nxt][0], bh[nxt][1], bh[nxt][2], bh[nxt][3], bHi + kb);
            ldsm4t(bh[nxt][4], bh[nxt][5], bh[nxt][6], bh[nxt][7], bHi + kb + 32);
            ldsm4t(bl[nxt][0], bl[nxt][1], bl[nxt][2], bl[nxt][3], bLo + kb);
            ldsm4t(bl[nxt][4], bl[nxt][5], bl[nxt][6], bl[nxt][7], bLo + kb + 32);
        }
        #pragma unroll
        for (int j = 0; j < 4; ++j) {
            mma16816(acc[j], ah[cur][0], ah[cur][1], ah[cur][2], ah[cur][3], bh[cur][2*j], bh[cur][2*j+1]);
            mma16816(acc[j], ah[cur][0], ah[cur][1], ah[cur][2], ah[cur][3], bl[cur][2*j], bl[cur][2*j+1]);
            mma16816(acc[j], al[cur][0], al[cur][1], al[cur][2], al[cur][3], bh[cur][2*j], bh[cur][2*j+1]);
        }
    }
}

__global__ __launch_bounds__(NTHR, 1)
void gat_ws_kernel(const float* __restrict__ h,
                   const float* __restrict__ W,
                   const float* __restrict__ a,
                   const float* __restrict__ adj,
                   float* __restrict__ out)
{
    extern __shared__ char smc[];
    const uint32_t sb = smem_u32(smc);
    float*  wh1 = (float*)(smc + R_WH1);
    float*  wh2 = (float*)(smc + R_WH2);
    float4* st4 = (float4*)(smc + R_ST4);
    float*  sav = (float*)(smc + R_AV);

    const int tid  = threadIdx.x;
    const int wid  = tid >> 5;
    const int lane = tid & 31;
    const int bt   = blockIdx.x;
    const bool producer = (wid >= 8);

    const int q  = lane & 3;
    const int rw = lane >> 2;
    const float* hB = h + (size_t)bt * N_NODES * F_IN;

    if (producer) {
        // ================== PRODUCER (warps 8-15, 256 threads) ==================
        const int ptid = tid - 256;
        int fr[8], fc4[8];
        #pragma unroll
        for (int it = 0; it < 8; ++it) {
            int idx = ptid + 256 * it;
            fr[it]  = idx >> 4;      // row 0..127
            fc4[it] = idx & 15;      // float4-col 0..15
        }
        // ---- W split + a vector ----
        {
            float4 v[8];
            #pragma unroll
            for (int it = 0; it < 8; ++it)
                v[it] = *(const float4*)(W + fr[it] * F_OUT + fc4[it] * 4);
            #pragma unroll
            for (int it = 0; it < 8; ++it) {
                uint2 hi, lo; split4(v[it], hi, lo);
                *(uint2*)(smc + R_W_HI + (fr[it] * PITCH + fc4[it] * 4) * 2) = hi;
                *(uint2*)(smc + R_W_LO + (fr[it] * PITCH + fc4[it] * 4) * 2) = lo;
            }
            if (ptid < 128) sav[ptid] = a[ptid];
        }
        // ---- GEMM1 A fills: chunks c = 0..3, (mc,kc) ----
        #pragma unroll
        for (int mc = 0; mc < 2; ++mc) {
            #pragma unroll
            for (int kc = 0; kc < 2; ++kc) {
                const int c = mc * 2 + kc, buf = c & 1;
                float4 v[8];
                #pragma unroll
                for (int it = 0; it < 8; ++it)
                    v[it] = *(const float4*)(hB + (size_t)(mc * 128 + fr[it]) * F_IN + kc * 64 + fc4[it] * 4);
                if (c >= 2) bar_sync_id(BEMPTY(buf));
                #pragma unroll
                for (int it = 0; it < 8; ++it) {
                    uint2 hi, lo; split4(v[it], hi, lo);
                    *(uint2*)(smc + R_AB + (buf * 2) * AB_SIZE + (fr[it] * PITCH + fc4[it] * 4) * 2) = hi;
                    *(uint2*)(smc + R_AB + (buf * 2 + 1) * AB_SIZE + (fr[it] * PITCH + fc4[it] * 4) * 2) = lo;
                }
                bar_arrive_id(BFULL(buf));
            }
        }
        __syncthreads();   // join: wh1/wh2 complete

        // ---- phase 2 share (rows wid=8..15, stride 16) ----
        for (int i = wid; i < N_NODES; i += 16) {
            const float s = wh1[i];
            const float4* adjrow = (const float4*)(adj + (size_t)i * N_NODES);
            float4 a0 = __ldg(adjrow + lane * 2);
            float4 a1 = __ldg(adjrow + lane * 2 + 1);
            float4 w0 = *(const float4*)(wh2 + lane * 8);
            float4 w1 = *(const float4*)(wh2 + lane * 8 + 4);
            float ad[8] = {a0.x, a0.y, a0.z, a0.w, a1.x, a1.y, a1.z, a1.w};
            float wv[8] = {w0.x, w0.y, w0.z, w0.w, w1.x, w1.y, w1.z, w1.w};
            float vals[8];
            #pragma unroll
            for (int p = 0; p < 8; ++p) {
                float e = s + wv[p];
                e = e > 0.0f ? e : 0.01f * e;
                vals[p] = (ad[p] > 0.0f) ? e : -3.0e38f;
            }
            float m = vals[0];
            #pragma unroll
            for (int p = 1; p < 8; ++p) m = fmaxf(m, vals[p]);
            #pragma unroll
            for (int off = 16; off > 0; off >>= 1)
                m = fmaxf(m, __shfl_xor_sync(0xffffffffu, m, off));
            float sum = 0.0f;
            #pragma unroll
            for (int p = 0; p < 8; ++p)
                sum += (vals[p] > -1.0e38f) ? __expf(vals[p] - m) : 0.0f;
            #pragma unroll
            for (int off = 16; off > 0; off >>= 1)
                sum += __shfl_xor_sync(0xffffffffu, sum, off);
            if (lane == 0) st4[i] = make_float4(s, m, 1.0f / sum, 0.0f);
        }
        __syncthreads();   // stats visible

        // ---- GEMM2 alpha fills: chunks c = 4..11, (mc,kc 0..3) ----
        #pragma unroll
        for (int mc = 0; mc < 2; ++mc) {
            #pragma unroll
            for (int kc = 0; kc < 4; ++kc) {
                const int c = 4 + mc * 4 + kc, buf = c & 1;
                float4 av[8];
                #pragma unroll
                for (int it = 0; it < 8; ++it)
                    av[it] = __ldg((const float4*)(adj + (size_t)(mc * 128 + fr[it]) * N_NODES + kc * 64 + fc4[it] * 4));
                bar_sync_id(BEMPTY(buf));
                #pragma unroll
                for (int it = 0; it < 8; ++it) {
                    float4 st = st4[mc * 128 + fr[it]];
                    float4 w = *(const float4*)(wh2 + kc * 64 + fc4[it] * 4);
                    float4 pv;
                    float e;
                    e = st.x + w.x; e = e > 0.f ? e : 0.01f * e; pv.x = (av[it].x > 0.f) ? __expf(e - st.y) * st.z : 0.f;
                    e = st.x + w.y; e = e > 0.f ? e : 0.01f * e; pv.y = (av[it].y > 0.f) ? __expf(e - st.y) * st.z : 0.f;
                    e = st.x + w.z; e = e > 0.f ? e : 0.01f * e; pv.z = (av[it].z > 0.f) ? __expf(e - st.y) * st.z : 0.f;
                    e = st.x + w.w; e = e > 0.f ? e : 0.01f * e; pv.w = (av[it].w > 0.f) ? __expf(e - st.y) * st.z : 0.f;
                    uint2 hi, lo; split4(pv, hi, lo);
                    *(uint2*)(smc + R_AB + (buf * 2) * AB_SIZE + (fr[it] * PITCH + fc4[it] * 4) * 2) = hi;
                    *(uint2*)(smc + R_AB + (buf * 2 + 1) * AB_SIZE + (fr[it] * PITCH + fc4[it] * 4) * 2) = lo;
                }
                bar_arrive_id(BFULL(buf));
            }
        }
    } else {
        // ================== CONSUMER (warps 0-7, 256 threads) ==================
        const uint32_t laneRow = (uint32_t)(lane & 15);
        const uint32_t laneCol = (uint32_t)((lane >> 4) * 8);
        const uint32_t aOffB  = ((wid * 16 + laneRow) * PITCH + laneCol) * 2;
        const uint32_t bOff0  = (laneRow * PITCH + 0  + laneCol) * 2;
        const uint32_t bOff1  = (laneRow * PITCH + 32 + laneCol) * 2;

        // ---- GEMM1 ----
        #pragma unroll
        for (int mc = 0; mc < 2; ++mc) {
            float acc[2][4][4] = {};
            #pragma unroll
            for (int kc = 0; kc < 2; ++kc) {
                const int c = mc * 2 + kc, buf = c & 1;
                bar_sync_id(BFULL(buf));
                const uint32_t aHi = sb + R_AB + (buf * 2) * AB_SIZE + aOffB;
                const uint32_t aLo = aHi + AB_SIZE;
                const uint32_t bkk = (uint32_t)(kc * 64) * (PITCH * 2);
                gemm_chunk(acc[0], aHi, aLo, sb + R_W_HI + bkk + bOff0, sb + R_W_LO + bkk + bOff0);
                gemm_chunk(acc[1], aHi, aLo, sb + R_W_HI + bkk + bOff1, sb + R_W_LO + bkk + bOff1);
                bar_arrive_id(BEMPTY(buf));
            }
            // ---- epilogue1: Wh1/Wh2 + Wh -> split bf16 into B2 ----
            float p1l = 0.f, p1h = 0.f, p2l = 0.f, p2h = 0.f;
            #pragma unroll
            for (int nh = 0; nh < 2; ++nh) {
                #pragma unroll
                for (int j = 0; j < 4; ++j) {
                    int col = nh * 32 + 8 * j + 2 * q;
                    float a10 = sav[col], a11 = sav[col + 1];
                    float a20 = sav[64 + col], a21 = sav[64 + col + 1];
                    p1l += acc[nh][j][0] * a10 + acc[nh][j][1] * a11;
                    p1h += acc[nh][j][2] * a10 + acc[nh][j][3] * a11;
                    p2l += acc[nh][j][0] * a20 + acc[nh][j][1] * a21;
                    p2h += acc[nh][j][2] * a20 + acc[nh][j][3] * a21;
                }
            }
            #pragma unroll
            for (int off = 1; off <= 2; off <<= 1) {
                p1l += __shfl_xor_sync(0xffffffffu, p1l, off);
                p1h += __shfl_xor_sync(0xffffffffu, p1h, off);
                p2l += __shfl_xor_sync(0xffffffffu, p2l, off);
                p2h += __shfl_xor_sync(0xffffffffu, p2h, off);
            }
            const int row0 = mc * 128 + wid * 16 + rw;
            if (q == 0) {
                wh1[row0] = p1l; wh1[row0 + 8] = p1h;
                wh2[row0] = p2l; wh2[row0 + 8] = p2h;
            }
            #pragma unroll
            for (int nh = 0; nh < 2; ++nh) {
                #pragma unroll
                for (int j = 0; j < 4; ++j) {
                    int col = nh * 32 + 8 * j + 2 * q;
                    uint32_t hi, lo;
                    split2(acc[nh][j][0], acc[nh][j][1], hi, lo);
                    *(uint32_t*)(smc + R_B2_HI + (row0 * PITCH + col) * 2) = hi;
                    *(uint32_t*)(smc + R_B2_LO + (row0 * PITCH + col) * 2) = lo;
                    split2(acc[nh][j][2], acc[nh][j][3], hi, lo);
                    *(uint32_t*)(smc + R_B2_HI + ((row0 + 8) * PITCH + col) * 2) = hi;
                    *(uint32_t*)(smc + R_B2_LO + ((row0 + 8) * PITCH + col) * 2) = lo;
                }
            }
        }
        __syncthreads();   // wh1/wh2 + B2 complete

        // ---- phase 2 share (rows wid=0..7, stride 16) ----
        for (int i = wid; i < N_NODES; i += 16) {
            const float s = wh1[i];
            const float4* adjrow = (const float4*)(adj + (size_t)i * N_NODES);
            float4 a0 = __ldg(adjrow + lane * 2);
            float4 a1 = __ldg(adjrow + lane * 2 + 1);
            float4 w0 = *(const float4*)(wh2 + lane * 8);
            float4 w1 = *(const float4*)(wh2 + lane * 8 + 4);
            float ad[8] = {a0.x, a0.y, a0.z, a0.w, a1.x, a1.y, a1.z, a1.w};
            float wv[8] = {w0.x, w0.y, w0.z, w0.w, w1.x, w1.y, w1.z, w1.w};
            float vals[8];
            #pragma unroll
            for (int p = 0; p < 8; ++p) {
                float e = s + wv[p];
                e = e > 0.0f ? e : 0.01f * e;
                vals[p] = (ad[p] > 0.0f) ? e : -3.0e38f;
            }
            float m = vals[0];
            #pragma unroll
            for (int p = 1; p < 8; ++p) m = fmaxf(m, vals[p]);
            #pragma unroll
            for (int off = 16; off > 0; off >>= 1)
                m = fmaxf(m, __shfl_xor_sync(0xffffffffu, m, off));
            float sum = 0.0f;
            #pragma unroll
            for (int p = 0; p < 8; ++p)
                sum += (vals[p] > -1.0e38f) ? __expf(vals[p] - m) : 0.0f;
            #pragma unroll
            for (int off = 16; off > 0; off >>= 1)
                sum += __shfl_xor_sync(0xffffffffu, sum, off);
            if (lane == 0) st4[i] = make_float4(s, m, 1.0f / sum, 0.0f);
        }
        __syncthreads();   // stats visible

        // ---- GEMM2 ----
        float* outB = out + (size_t)bt * N_NODES * F_OUT;
        #pragma unroll
        for (int mc = 0; mc < 2; ++mc) {
            float acc[2][4][4] = {};
            #pragma unroll
            for (int kc = 0; kc < 4; ++kc) {
                const int c = 4 + mc * 4 + kc, buf = c & 1;
                bar_sync_id(BFULL(buf));
                const uint32_t aHi = sb + R_AB + (buf * 2) * AB_SIZE + aOffB;
                const uint32_t aLo = aHi + AB_SIZE;
                const uint32_t bkk = (uint32_t)(kc * 64) * (PITCH * 2);
                gemm_chunk(acc[0], aHi, aLo, sb + R_B2_HI + bkk + bOff0, sb + R_B2_LO + bkk + bOff0);
                gemm_chunk(acc[1], aHi, aLo, sb + R_B2_HI + bkk + bOff1, sb + R_B2_LO + bkk + bOff1);
                bar_arrive_id(BEMPTY(buf));
            }
            // ---- epilogue2: ELU + store ----
            const int row0 = mc * 128 + wid * 16 + rw;
            #pragma unroll
            for (int nh = 0; nh < 2; ++nh) {
                #pragma unroll
                for (int j = 0; j < 4; ++j) {
                    int col = nh * 32 + 8 * j + 2 * q;
                    float x0 = acc[nh][j][0], x1 = acc[nh][j][1];
                    float x2 = acc[nh][j][2], x3 = acc[nh][j][3];
                    float2 v0, v1;
                    v0.x = x0 > 0.0f ? x0 : expm1f(x0);
                    v0.y = x1 > 0.0f ? x1 : expm1f(x1);
                    v1.x = x2 > 0.0f ? x2 : expm1f(x2);
                    v1.y = x3 > 0.0f ? x3 : expm1f(x3);
                    *(float2*)(outB + (size_t)row0 * F_OUT + col)       = v0;
                    *(float2*)(outB + (size_t)(row0 + 8) * F_OUT + col) = v1;
                }
            }
        }
    }
}

extern "C" void kernel_launch(void* const* d_in, const int* in_sizes, int n_in,
                              void* d_out, int out_size)
{
    const float* h   = (const float*)d_in[0];   // (8,64,256,128)
    const float* W   = (const float*)d_in[1];   // (128,64)
    const float* a   = (const float*)d_in[2];   // (128,1)
    const float* adj = (const float*)d_in[3];   // (256,256)
    float* out = (float*)d_out;                 // (8,64,256,64)

    cudaFuncSetAttribute(gat_ws_kernel,
                         cudaFuncAttributeMaxDynamicSharedMemorySize, SM_TOTAL);
    gat_ws_kernel<<<BT_TOTAL, NTHR, SM_TOTAL>>>(h, W, a, adj, out);
}

// round 10
// speedup vs baseline: 1.0499x; 1.0499x over previous
#include <cuda_runtime.h>
#include <cuda_bf16.h>
#include <stdint.h>
#include <math.h>

#define N_NODES 256
#define F_IN    128
#define F_OUT   64
#define BT_TOTAL 512
#define NTHR    512

// bf16 row pitch 72 elems (144B): 144 mod 128 = 16 -> conflict-free ldmatrix
#define PITCH   72

// ---- smem byte offsets ----
// A chunk block [256 m][64 k] bf16 pitch 72 = 36864 B
#define R_AB0_HI 0
#define R_AB0_LO 36864
#define R_AB1_HI 73728
#define R_AB1_LO 110592
#define R_W_HI   147456                 // W [128 k][64 n] bf16 pitch 72
#define R_W_LO   165888
#define R_B2_HI  R_AB0_HI               // Wh [256 k][64 n] aliases AB0 (dead by epilogue1)
#define R_B2_LO  R_AB0_LO
#define R_SP1    184320                 // [2][256] f32 Wh1 partials
#define R_SP2    186368                 // [2][256] f32 Wh2 partials
#define R_WH1    188416                 // [256] f32
#define R_WH2    189440                 // [256] f32
#define R_ST4    190464                 // [256] float4 (wh1, rmax, rinv, _)
#define R_AV     194560                 // a vector [128] f32
#define SM_TOTAL 195072

static __device__ __forceinline__ uint32_t smem_u32(const void* p) {
    uint32_t a;
    asm("{ .reg .u64 t; cvta.to.shared.u64 t, %1; cvt.u32.u64 %0, t; }" : "=r"(a) : "l"(p));
    return a;
}
static __device__ __forceinline__ void ldsm4(uint32_t& r0, uint32_t& r1, uint32_t& r2, uint32_t& r3, uint32_t addr) {
    asm volatile("ldmatrix.sync.aligned.m8n8.x4.shared.b16 {%0,%1,%2,%3}, [%4];"
                 : "=r"(r0), "=r"(r1), "=r"(r2), "=r"(r3) : "r"(addr));
}
static __device__ __forceinline__ void ldsm4t(uint32_t& r0, uint32_t& r1, uint32_t& r2, uint32_t& r3, uint32_t addr) {
    asm volatile("ldmatrix.sync.aligned.m8n8.x4.trans.shared.b16 {%0,%1,%2,%3}, [%4];"
                 : "=r"(r0), "=r"(r1), "=r"(r2), "=r"(r3) : "r"(addr));
}
static __device__ __forceinline__ void mma16816(float* c,
        uint32_t a0, uint32_t a1, uint32_t a2, uint32_t a3, uint32_t b0, uint32_t b1) {
    asm volatile("mma.sync.aligned.m16n8k16.row.col.f32.bf16.bf16.f32 "
                 "{%0,%1,%2,%3}, {%4,%5,%6,%7}, {%8,%9}, {%0,%1,%2,%3};"
                 : "+f"(c[0]), "+f"(c[1]), "+f"(c[2]), "+f"(c[3])
                 : "r"(a0), "r"(a1), "r"(a2), "r"(a3), "r"(b0), "r"(b1));
}
// packed split: hi word = {bf16(y), bf16(x)}, lo word = residuals
static __device__ __forceinline__ void split2(float x, float y, uint32_t& hi, uint32_t& lo) {
    asm("cvt.rn.bf16x2.f32 %0, %1, %2;" : "=r"(hi) : "f"(y), "f"(x));
    float rx = __uint_as_float(hi << 16);
    float ry = __uint_as_float(hi & 0xFFFF0000u);
    asm("cvt.rn.bf16x2.f32 %0, %1, %2;" : "=r"(lo) : "f"(y - ry), "f"(x - rx));
}
static __device__ __forceinline__ void split4(float4 v, uint2& hi, uint2& lo) {
    split2(v.x, v.y, hi.x, lo.x);
    split2(v.z, v.w, hi.y, lo.y);
}

// 32m x 32n warp GEMM over 64 k (4 ksteps), 3-term bf16 split.
// acc0 = rows [base, base+16), acc1 = rows [base+16, base+32).
static __device__ __forceinline__ void gemm_chunk32(
    float (&acc0)[4][4], float (&acc1)[4][4],
    uint32_t aHi, uint32_t aLo, uint32_t bHi, uint32_t bLo)
{
    #pragma unroll
    for (int k0 = 0; k0 < 4; ++k0) {
        const int ka = k0 * 32;
        const int kb = k0 * 16 * (PITCH * 2);
        uint32_t a0h[4], a1h[4], a0l[4], a1l[4], bh[8], bl[8];
        ldsm4(a0h[0], a0h[1], a0h[2], a0h[3], aHi + ka);
        ldsm4(a1h[0], a1h[1], a1h[2], a1h[3], aHi + 16 * (PITCH * 2) + ka);
        ldsm4(a0l[0], a0l[1], a0l[2], a0l[3], aLo + ka);
        ldsm4(a1l[0], a1l[1], a1l[2], a1l[3], aLo + 16 * (PITCH * 2) + ka);
        ldsm4t(bh[0], bh[1], bh[2], bh[3], bHi + kb);
        ldsm4t(bh[4], bh[5], bh[6], bh[7], bHi + kb + 32);
        ldsm4t(bl[0], bl[1], bl[2], bl[3], bLo + kb);
        ldsm4t(bl[4], bl[5], bl[6], bl[7], bLo + kb + 32);
        #pragma unroll
        for (int j = 0; j < 4; ++j) {
            mma16816(acc0[j], a0h[0], a0h[1], a0h[2], a0h[3], bh[2*j], bh[2*j+1]);
            mma16816(acc0[j], a0h[0], a0h[1], a0h[2], a0h[3], bl[2*j], bl[2*j+1]);
            mma16816(acc0[j], a0l[0], a0l[1], a0l[2], a0l[3], bh[2*j], bh[2*j+1]);
            mma16816(acc1[j], a1h[0], a1h[1], a1h[2], a1h[3], bh[2*j], bh[2*j+1]);
            mma16816(acc1[j], a1h[0], a1h[1], a1h[2], a1h[3], bl[2*j], bl[2*j+1]);
            mma16816(acc1[j], a1l[0], a1l[1], a1l[2], a1l[3], bh[2*j], bh[2*j+1]);
        }
    }
}

__global__ __launch_bounds__(NTHR, 1)
void gat_mma_kernel(const float* __restrict__ h,
                    const float* __restrict__ W,
                    const float* __restrict__ a,
                    const float* __restrict__ adj,
                    float* __restrict__ out)
{
    extern __shared__ char smc[];
    const uint32_t sb = smem_u32(smc);
    float*  sP1 = (float*)(smc + R_SP1);
    float*  sP2 = (float*)(smc + R_SP2);
    float*  wh1 = (float*)(smc + R_WH1);
    float*  wh2 = (float*)(smc + R_WH2);
    float4* st4 = (float4*)(smc + R_ST4);
    float*  sav = (float*)(smc + R_AV);

    const int tid  = threadIdx.x;
    const int wid  = tid >> 5;
    const int lane = tid & 31;
    const int bt   = blockIdx.x;

    const int mt = wid >> 1;           // m-tile 0..7 (32 rows)
    const int nh = wid & 1;            // n-half 0..1 (32 cols)
    const int mrow0 = mt * 32;
    const int ncol0 = nh * 32;
    const int q  = lane & 3;
    const int rw = lane >> 2;

    const float* hB = h + (size_t)bt * N_NODES * F_IN;

    const uint32_t laneRow = (uint32_t)(lane & 15);
    const uint32_t laneCol = (uint32_t)((lane >> 4) * 8);
    const uint32_t aOff = ((mrow0 + laneRow) * PITCH + laneCol) * 2;
    const uint32_t bOff = (laneRow * PITCH + ncol0 + laneCol) * 2;

    // chunk fill index decomposition: 4096 float4 per [256][64] chunk, 8/thread
    int fr[8], fc4[8];
    #pragma unroll
    for (int it = 0; it < 8; ++it) {
        int idx = tid + NTHR * it;
        fr[it]  = idx >> 4;      // row 0..255
        fc4[it] = idx & 15;      // float4-col 0..15
    }

    // ================= fills: W, h kc0 -> AB0, h kc1 -> AB1, a =================
    {
        #pragma unroll
        for (int it = 0; it < 4; ++it) {
            int idx = tid + NTHR * it;
            int r = idx >> 4, c4 = idx & 15;
            float4 v = *(const float4*)(W + r * F_OUT + c4 * 4);
            uint2 hi, lo; split4(v, hi, lo);
            *(uint2*)(smc + R_W_HI + (r * PITCH + c4 * 4) * 2) = hi;
            *(uint2*)(smc + R_W_LO + (r * PITCH + c4 * 4) * 2) = lo;
        }
        float4 v0[8], v1[8];
        #pragma unroll
        for (int it = 0; it < 8; ++it)
            v0[it] = *(const float4*)(hB + (size_t)fr[it] * F_IN + fc4[it] * 4);
        #pragma unroll
        for (int it = 0; it < 8; ++it)
            v1[it] = *(const float4*)(hB + (size_t)fr[it] * F_IN + 64 + fc4[it] * 4);
        #pragma unroll
        for (int it = 0; it < 8; ++it) {
            int off = (fr[it] * PITCH + fc4[it] * 4) * 2;
            uint2 hi, lo;
            split4(v0[it], hi, lo);
            *(uint2*)(smc + R_AB0_HI + off) = hi;
            *(uint2*)(smc + R_AB0_LO + off) = lo;
            split4(v1[it], hi, lo);
            *(uint2*)(smc + R_AB1_HI + off) = hi;
            *(uint2*)(smc + R_AB1_LO + off) = lo;
        }
        if (tid < 128) sav[tid] = a[tid];
    }
    __syncthreads();

    // ================= GEMM1: Wh = h @ W (full 256m x 64n x 128k) =================
    {
        float acc0[4][4] = {}, acc1[4][4] = {};
        gemm_chunk32(acc0, acc1, sb + R_AB0_HI + aOff, sb + R_AB0_LO + aOff,
                     sb + R_W_HI + bOff, sb + R_W_LO + bOff);
        gemm_chunk32(acc0, acc1, sb + R_AB1_HI + aOff, sb + R_AB1_LO + aOff,
                     sb + R_W_HI + 64 * (PITCH * 2) + bOff,
                     sb + R_W_LO + 64 * (PITCH * 2) + bOff);

        // ---- epilogue1: Wh1/Wh2 partials + Wh -> split bf16 into B2 (=AB0) ----
        float p1l[2] = {0.f, 0.f}, p1h[2] = {0.f, 0.f};
        float p2l[2] = {0.f, 0.f}, p2h[2] = {0.f, 0.f};
        #pragma unroll
        for (int s = 0; s < 2; ++s) {
            float (*acc)[4] = s ? acc1 : acc0;
            #pragma unroll
            for (int j = 0; j < 4; ++j) {
                int col = ncol0 + 8 * j + 2 * q;
                float a10 = sav[col], a11 = sav[col + 1];
                float a20 = sav[64 + col], a21 = sav[64 + col + 1];
                p1l[s] += acc[j][0] * a10 + acc[j][1] * a11;
                p1h[s] += acc[j][2] * a10 + acc[j][3] * a11;
                p2l[s] += acc[j][0] * a20 + acc[j][1] * a21;
                p2h[s] += acc[j][2] * a20 + acc[j][3] * a21;
            }
        }
        #pragma unroll
        for (int off = 1; off <= 2; off <<= 1) {
            #pragma unroll
            for (int s = 0; s < 2; ++s) {
                p1l[s] += __shfl_xor_sync(0xffffffffu, p1l[s], off);
                p1h[s] += __shfl_xor_sync(0xffffffffu, p1h[s], off);
                p2l[s] += __shfl_xor_sync(0xffffffffu, p2l[s], off);
                p2h[s] += __shfl_xor_sync(0xffffffffu, p2h[s], off);
            }
        }
        if (q == 0) {
            #pragma unroll
            for (int s = 0; s < 2; ++s) {
                int r0 = mrow0 + 16 * s + rw;
                sP1[nh * 256 + r0]     = p1l[s];
                sP1[nh * 256 + r0 + 8] = p1h[s];
                sP2[nh * 256 + r0]     = p2l[s];
                sP2[nh * 256 + r0 + 8] = p2h[s];
            }
        }
        #pragma unroll
        for (int s = 0; s < 2; ++s) {
            float (*acc)[4] = s ? acc1 : acc0;
            int r0 = mrow0 + 16 * s + rw;
            #pragma unroll
            for (int j = 0; j < 4; ++j) {
                int col = ncol0 + 8 * j + 2 * q;
                uint32_t hi, lo;
                split2(acc[j][0], acc[j][1], hi, lo);
                *(uint32_t*)(smc + R_B2_HI + (r0 * PITCH + col) * 2) = hi;
                *(uint32_t*)(smc + R_B2_LO + (r0 * PITCH + col) * 2) = lo;
                split2(acc[j][2], acc[j][3], hi, lo);
                *(uint32_t*)(smc + R_B2_HI + ((r0 + 8) * PITCH + col) * 2) = hi;
                *(uint32_t*)(smc + R_B2_LO + ((r0 + 8) * PITCH + col) * 2) = lo;
            }
        }
    }
    __syncthreads();

    // ---- combine Wh1/Wh2 partials ----
    if (tid < 256) {
        wh1[tid] = sP1[tid] + sP1[256 + tid];
        wh2[tid] = sP2[tid] + sP2[256 + tid];
    }
    __syncthreads();

    // ================= Phase 2: softmax stats =================
    for (int i = wid; i < N_NODES; i += 16) {
        const float s = wh1[i];
        const float4* adjrow = (const float4*)(adj + (size_t)i * N_NODES);
        float4 a0 = __ldg(adjrow + lane * 2);
        float4 a1 = __ldg(adjrow + lane * 2 + 1);
        float4 w0 = *(const float4*)(wh2 + lane * 8);
        float4 w1 = *(const float4*)(wh2 + lane * 8 + 4);
        float ad[8] = {a0.x, a0.y, a0.z, a0.w, a1.x, a1.y, a1.z, a1.w};
        float wv[8] = {w0.x, w0.y, w0.z, w0.w, w1.x, w1.y, w1.z, w1.w};
        float vals[8];
        #pragma unroll
        for (int p = 0; p < 8; ++p) {
            float e = s + wv[p];
            e = e > 0.0f ? e : 0.01f * e;
            vals[p] = (ad[p] > 0.0f) ? e : -3.0e38f;
        }
        float m = vals[0];
        #pragma unroll
        for (int p = 1; p < 8; ++p) m = fmaxf(m, vals[p]);
        #pragma unroll
        for (int off = 16; off > 0; off >>= 1)
            m = fmaxf(m, __shfl_xor_sync(0xffffffffu, m, off));
        float sum = 0.0f;
        #pragma unroll
        for (int p = 0; p < 8; ++p)
            sum += (vals[p] > -1.0e38f) ? __expf(vals[p] - m) : 0.0f;
        #pragma unroll
        for (int off = 16; off > 0; off >>= 1)
            sum += __shfl_xor_sync(0xffffffffu, sum, off);
        if (lane == 0) st4[i] = make_float4(s, m, 1.0f / sum, 0.0f);
    }
    __syncthreads();

    // ================= Phase 3: h' = alpha @ Wh (4 x 64k chunks in AB1) =================
    float* outB = out + (size_t)bt * N_NODES * F_OUT;
    float4 reg[8];
    // prefill chunk 0
    #pragma unroll
    for (int it = 0; it < 8; ++it)
        reg[it] = __ldg((const float4*)(adj + (size_t)fr[it] * N_NODES + fc4[it] * 4));
    #pragma unroll
    for (int it = 0; it < 8; ++it) {
        float4 st = st4[fr[it]];
        float4 w = *(const float4*)(wh2 + fc4[it] * 4);
        float4 pv; float e;
        e = st.x + w.x; e = e > 0.f ? e : 0.01f * e; pv.x = (reg[it].x > 0.f) ? __expf(e - st.y) * st.z : 0.f;
        e = st.x + w.y; e = e > 0.f ? e : 0.01f * e; pv.y = (reg[it].y > 0.f) ? __expf(e - st.y) * st.z : 0.f;
        e = st.x + w.z; e = e > 0.f ? e : 0.01f * e; pv.z = (reg[it].z > 0.f) ? __expf(e - st.y) * st.z : 0.f;
        e = st.x + w.w; e = e > 0.f ? e : 0.01f * e; pv.w = (reg[it].w > 0.f) ? __expf(e - st.y) * st.z : 0.f;
        int off = (fr[it] * PITCH + fc4[it] * 4) * 2;
        uint2 hi, lo; split4(pv, hi, lo);
        *(uint2*)(smc + R_AB1_HI + off) = hi;
        *(uint2*)(smc + R_AB1_LO + off) = lo;
    }
    __syncthreads();

    float acc0[4][4] = {}, acc1[4][4] = {};
    #pragma unroll
    for (int kc = 0; kc < 4; ++kc) {
        if (kc < 3) {
            #pragma unroll
            for (int it = 0; it < 8; ++it)
                reg[it] = __ldg((const float4*)(adj + (size_t)fr[it] * N_NODES + (kc + 1) * 64 + fc4[it] * 4));
        }
        gemm_chunk32(acc0, acc1, sb + R_AB1_HI + aOff, sb + R_AB1_LO + aOff,
                     sb + R_B2_HI + (uint32_t)(kc * 64) * (PITCH * 2) + bOff,
                     sb + R_B2_LO + (uint32_t)(kc * 64) * (PITCH * 2) + bOff);
        if (kc < 3) {
            // exp transform in regs (before barrier: overlaps warp skew)
            #pragma unroll
            for (int it = 0; it < 8; ++it) {
                float4 st = st4[fr[it]];
                float4 w = *(const float4*)(wh2 + (kc + 1) * 64 + fc4[it] * 4);
                float4 pv; float e;
                e = st.x + w.x; e = e > 0.f ? e : 0.01f * e; pv.x = (reg[it].x > 0.f) ? __expf(e - st.y) * st.z : 0.f;
                e = st.x + w.y; e = e > 0.f ? e : 0.01f * e; pv.y = (reg[it].y > 0.f) ? __expf(e - st.y) * st.z : 0.f;
                e = st.x + w.z; e = e > 0.f ? e : 0.01f * e; pv.z = (reg[it].z > 0.f) ? __expf(e - st.y) * st.z : 0.f;
                e = st.x + w.w; e = e > 0.f ? e : 0.01f * e; pv.w = (reg[it].w > 0.f) ? __expf(e - st.y) * st.z : 0.f;
                reg[it] = pv;
            }
            __syncthreads();    // all reads of AB1 (chunk kc) done
            #pragma unroll
            for (int it = 0; it < 8; ++it) {
                int off = (fr[it] * PITCH + fc4[it] * 4) * 2;
                uint2 hi, lo; split4(reg[it], hi, lo);
                *(uint2*)(smc + R_AB1_HI + off) = hi;
                *(uint2*)(smc + R_AB1_LO + off) = lo;
            }
            __syncthreads();    // chunk kc+1 visible
        }
    }

    // ---- epilogue2: ELU + store ----
    #pragma unroll
    for (int s = 0; s < 2; ++s) {
        float (*acc)[4] = s ? acc1 : acc0;
        int r0 = mrow0 + 16 * s + rw;
        #pragma unroll
        for (int j = 0; j < 4; ++j) {
            int col = ncol0 + 8 * j + 2 * q;
            float x0 = acc[j][0], x1 = acc[j][1], x2 = acc[j][2], x3 = acc[j][3];
            float2 v0, v1;
            v0.x = x0 > 0.0f ? x0 : expm1f(x0);
            v0.y = x1 > 0.0f ? x1 : expm1f(x1);
            v1.x = x2 > 0.0f ? x2 : expm1f(x2);
            v1.y = x3 > 0.0f ? x3 : expm1f(x3);
            *(float2*)(outB + (size_t)r0 * F_OUT + col)       = v0;
            *(float2*)(outB + (size_t)(r0 + 8) * F_OUT + col) = v1;
        }
    }
}

extern "C" void kernel_launch(void* const* d_in, const int* in_sizes, int n_in,
                              void* d_out, int out_size)
{
    const float* h   = (const float*)d_in[0];   // (8,64,256,128)
    const float* W   = (const float*)d_in[1];   // (128,64)
    const float* a   = (const float*)d_in[2];   // (128,1)
    const float* adj = (const float*)d_in[3];   // (256,256)
    float* out = (float*)d_out;                 // (8,64,256,64)

    cudaFuncSetAttribute(gat_mma_kernel,
                         cudaFuncAttributeMaxDynamicSharedMemorySize, SM_TOTAL);
    gat_mma_kernel<<<BT_TOTAL, NTHR, SM_TOTAL>>>(h, W, a, adj, out);
}

// round 12
// speedup vs baseline: 1.0513x; 1.0013x over previous
#include <cuda_runtime.h>
#include <cuda_bf16.h>
#include <stdint.h>
#include <math.h>

#define N_NODES 256
#define F_IN    128
#define F_OUT   64
#define BT_TOTAL 512

// ---- global scratch (static __device__, no allocation) ----
__device__ uint32_t g_wh_hi[BT_TOTAL * N_NODES * 32];   // packed bf16x2, [bt][row][32]
__device__ uint32_t g_wh_lo[BT_TOTAL * N_NODES * 32];
__device__ float    g_wh1[BT_TOTAL * N_NODES];
__device__ float    g_wh2[BT_TOTAL * N_NODES];

// ================= kernel 1 smem layout (bytes) =================
// A tile [128 m][128 k] bf16, pitch 136 elem (272B)
#define K1_A_HI  0
#define K1_A_LO  34816
#define K1_W_HI  69632          // W [128 k][64 n] bf16, pitch 72 (144B)
#define K1_W_LO  88064
#define K1_SP1   106496         // [2][128] f32
#define K1_SP2   107520
#define K1_AV    108544         // [128] f32
#define K1_TOTAL 109056

// ================= kernel 2 smem layout (bytes) =================
// B2 [256 k][64 n] bf16 pitch 72; A [128 m][64 k] bf16 pitch 72
#define K2_B2_HI 0
#define K2_B2_LO 36864
#define K2_A_HI  73728
#define K2_A_LO  92160
#define K2_WH2   110592         // [256] f32
#define K2_ST4   111616         // [128] float4 (wh1, rmax, rinv, _)
#define K2_TOTAL 113664

static __device__ __forceinline__ uint32_t smem_u32(const void* p) {
    uint32_t a;
    asm("{ .reg .u64 t; cvta.to.shared.u64 t, %1; cvt.u32.u64 %0, t; }" : "=r"(a) : "l"(p));
    return a;
}
static __device__ __forceinline__ void ldsm4(uint32_t& r0, uint32_t& r1, uint32_t& r2, uint32_t& r3, uint32_t addr) {
    asm volatile("ldmatrix.sync.aligned.m8n8.x4.shared.b16 {%0,%1,%2,%3}, [%4];"
                 : "=r"(r0), "=r"(r1), "=r"(r2), "=r"(r3) : "r"(addr));
}
static __device__ __forceinline__ void ldsm4t(uint32_t& r0, uint32_t& r1, uint32_t& r2, uint32_t& r3, uint32_t addr) {
    asm volatile("ldmatrix.sync.aligned.m8n8.x4.trans.shared.b16 {%0,%1,%2,%3}, [%4];"
                 : "=r"(r0), "=r"(r1), "=r"(r2), "=r"(r3) : "r"(addr));
}
static __device__ __forceinline__ void mma16816(float* c,
        uint32_t a0, uint32_t a1, uint32_t a2, uint32_t a3, uint32_t b0, uint32_t b1) {
    asm volatile("mma.sync.aligned.m16n8k16.row.col.f32.bf16.bf16.f32 "
                 "{%0,%1,%2,%3}, {%4,%5,%6,%7}, {%8,%9}, {%0,%1,%2,%3};"
                 : "+f"(c[0]), "+f"(c[1]), "+f"(c[2]), "+f"(c[3])
                 : "r"(a0), "r"(a1), "r"(a2), "r"(a3), "r"(b0), "r"(b1));
}
static __device__ __forceinline__ void split2(float x, float y, uint32_t& hi, uint32_t& lo) {
    asm("cvt.rn.bf16x2.f32 %0, %1, %2;" : "=r"(hi) : "f"(y), "f"(x));
    float rx = __uint_as_float(hi << 16);
    float ry = __uint_as_float(hi & 0xFFFF0000u);
    asm("cvt.rn.bf16x2.f32 %0, %1, %2;" : "=r"(lo) : "f"(y - ry), "f"(x - rx));
}
static __device__ __forceinline__ void split4(float4 v, uint2& hi, uint2& lo) {
    split2(v.x, v.y, hi.x, lo.x);
    split2(v.z, v.w, hi.y, lo.y);
}

// 32m x 32n warp GEMM over KSTEPS*16 k, 3-term bf16 split.
// A16 = byte offset to rows+16; AKS = per-kstep byte advance in A rows;
// BKS = per-kstep byte advance in B (16 k-rows).
template<int KSTEPS, int A16, int BKS>
static __device__ __forceinline__ void gemm32(
    float (&acc0)[4][4], float (&acc1)[4][4],
    uint32_t aHi, uint32_t aLo, uint32_t bHi, uint32_t bLo)
{
    #pragma unroll
    for (int k0 = 0; k0 < KSTEPS; ++k0) {
        const int ka = k0 * 32;
        const int kb = k0 * BKS;
        uint32_t a0h[4], a1h[4], a0l[4], a1l[4], bh[8], bl[8];
        ldsm4(a0h[0], a0h[1], a0h[2], a0h[3], aHi + ka);
        ldsm4(a1h[0], a1h[1], a1h[2], a1h[3], aHi + A16 + ka);
        ldsm4(a0l[0], a0l[1], a0l[2], a0l[3], aLo + ka);
        ldsm4(a1l[0], a1l[1], a1l[2], a1l[3], aLo + A16 + ka);
        ldsm4t(bh[0], bh[1], bh[2], bh[3], bHi + kb);
        ldsm4t(bh[4], bh[5], bh[6], bh[7], bHi + kb + 32);
        ldsm4t(bl[0], bl[1], bl[2], bl[3], bLo + kb);
        ldsm4t(bl[4], bl[5], bl[6], bl[7], bLo + kb + 32);
        #pragma unroll
        for (int j = 0; j < 4; ++j) {
            mma16816(acc0[j], a0h[0], a0h[1], a0h[2], a0h[3], bh[2*j], bh[2*j+1]);
            mma16816(acc0[j], a0h[0], a0h[1], a0h[2], a0h[3], bl[2*j], bl[2*j+1]);
            mma16816(acc0[j], a0l[0], a0l[1], a0l[2], a0l[3], bh[2*j], bh[2*j+1]);
            mma16816(acc1[j], a1h[0], a1h[1], a1h[2], a1h[3], bh[2*j], bh[2*j+1]);
            mma16816(acc1[j], a1h[0], a1h[1], a1h[2], a1h[3], bl[2*j], bl[2*j+1]);
            mma16816(acc1[j], a1l[0], a1l[1], a1l[2], a1l[3], bh[2*j], bh[2*j+1]);
        }
    }
}

// ===================== Kernel 1: Wh = h @ W, Wh1/Wh2 =====================
__global__ __launch_bounds__(256, 2)
void gat_k1(const float* __restrict__ h,
            const float* __restrict__ W,
            const float* __restrict__ a)
{
    extern __shared__ char smc[];
    const uint32_t sb = smem_u32(smc);
    float* sP1 = (float*)(smc + K1_SP1);
    float* sP2 = (float*)(smc + K1_SP2);
    float* sav = (float*)(smc + K1_AV);

    const int tid  = threadIdx.x;
    const int wid  = tid >> 5;
    const int lane = tid & 31;
    const int bt   = blockIdx.x >> 1;
    const int mh   = blockIdx.x & 1;

    const int mt = wid >> 1;           // 0..3, 32 rows each
    const int nh = wid & 1;
    const int mrow0 = mt * 32;
    const int ncol0 = nh * 32;
    const int q  = lane & 3;
    const int rw = lane >> 2;

    const float* hB = h + ((size_t)bt * N_NODES + mh * 128) * F_IN;

    // ---- W fill (pitch 72) + a ----
    #pragma unroll
    for (int it = 0; it < 8; ++it) {
        int idx = tid + 256 * it;
        int r = idx >> 4, c4 = idx & 15;
        float4 v = *(const float4*)(W + r * F_OUT + c4 * 4);
        uint2 hi, lo; split4(v, hi, lo);
        *(uint2*)(smc + K1_W_HI + r * 144 + c4 * 8) = hi;
        *(uint2*)(smc + K1_W_LO + r * 144 + c4 * 8) = lo;
    }
    if (tid < 128) sav[tid] = a[tid];

    // ---- h tile fill: [128 m][128 k], pitch 136 ----
    #pragma unroll
    for (int it = 0; it < 16; ++it) {
        int idx = tid + 256 * it;
        int r = idx >> 5, c4 = idx & 31;
        float4 v = *(const float4*)(hB + (size_t)r * F_IN + c4 * 4);
        uint2 hi, lo; split4(v, hi, lo);
        *(uint2*)(smc + K1_A_HI + r * 272 + c4 * 8) = hi;
        *(uint2*)(smc + K1_A_LO + r * 272 + c4 * 8) = lo;
    }
    __syncthreads();

    // ---- GEMM1 (full K=128) ----
    const uint32_t laneRow = (uint32_t)(lane & 15);
    const uint32_t laneCol = (uint32_t)((lane >> 4) * 8);
    float acc0[4][4] = {}, acc1[4][4] = {};
    gemm32<8, 16 * 272, 16 * 144>(acc0, acc1,
        sb + K1_A_HI + (mrow0 + laneRow) * 272 + laneCol * 2,
        sb + K1_A_LO + (mrow0 + laneRow) * 272 + laneCol * 2,
        sb + K1_W_HI + laneRow * 144 + (ncol0 + laneCol) * 2,
        sb + K1_W_LO + laneRow * 144 + (ncol0 + laneCol) * 2);

    // ---- epilogue: Wh1/Wh2 partials + Wh -> global split-bf16 ----
    float p1l[2] = {0.f, 0.f}, p1h[2] = {0.f, 0.f};
    float p2l[2] = {0.f, 0.f}, p2h[2] = {0.f, 0.f};
    #pragma unroll
    for (int s = 0; s < 2; ++s) {
        float (*acc)[4] = s ? acc1 : acc0;
        #pragma unroll
        for (int j = 0; j < 4; ++j) {
            int col = ncol0 + 8 * j + 2 * q;
            float a10 = sav[col], a11 = sav[col + 1];
            float a20 = sav[64 + col], a21 = sav[64 + col + 1];
            p1l[s] += acc[j][0] * a10 + acc[j][1] * a11;
            p1h[s] += acc[j][2] * a10 + acc[j][3] * a11;
            p2l[s] += acc[j][0] * a20 + acc[j][1] * a21;
            p2h[s] += acc[j][2] * a20 + acc[j][3] * a21;
        }
    }
    #pragma unroll
    for (int off = 1; off <= 2; off <<= 1) {
        #pragma unroll
        for (int s = 0; s < 2; ++s) {
            p1l[s] += __shfl_xor_sync(0xffffffffu, p1l[s], off);
            p1h[s] += __shfl_xor_sync(0xffffffffu, p1h[s], off);
            p2l[s] += __shfl_xor_sync(0xffffffffu, p2l[s], off);
            p2h[s] += __shfl_xor_sync(0xffffffffu, p2h[s], off);
        }
    }
    if (q == 0) {
        #pragma unroll
        for (int s = 0; s < 2; ++s) {
            int r0 = mrow0 + 16 * s + rw;
            sP1[nh * 128 + r0]     = p1l[s];
            sP1[nh * 128 + r0 + 8] = p1h[s];
            sP2[nh * 128 + r0]     = p2l[s];
            sP2[nh * 128 + r0 + 8] = p2h[s];
        }
    }
    uint32_t* whHi = g_wh_hi + ((size_t)bt * N_NODES + mh * 128) * 32;
    uint32_t* whLo = g_wh_lo + ((size_t)bt * N_NODES + mh * 128) * 32;
    #pragma unroll
    for (int s = 0; s < 2; ++s) {
        float (*acc)[4] = s ? acc1 : acc0;
        int r0 = mrow0 + 16 * s + rw;
        #pragma unroll
        for (int j = 0; j < 4; ++j) {
            int cp = (ncol0 >> 1) + 4 * j + q;   // col-pair index 0..31
            uint32_t hi, lo;
            split2(acc[j][0], acc[j][1], hi, lo);
            whHi[r0 * 32 + cp] = hi;
            whLo[r0 * 32 + cp] = lo;
            split2(acc[j][2], acc[j][3], hi, lo);
            whHi[(r0 + 8) * 32 + cp] = hi;
            whLo[(r0 + 8) * 32 + cp] = lo;
        }
    }
    __syncthreads();
    if (tid < 128) {
        size_t gi = (size_t)bt * N_NODES + mh * 128 + tid;
        g_wh1[gi] = sP1[tid] + sP1[128 + tid];
        g_wh2[gi] = sP2[tid] + sP2[128 + tid];
    }
}

// ===================== Kernel 2: softmax + alpha @ Wh + ELU =====================
__global__ __launch_bounds__(256, 2)
void gat_k2(const float* __restrict__ adj,
            float* __restrict__ out)
{
    extern __shared__ char smc[];
    const uint32_t sb = smem_u32(smc);
    float*  wh2 = (float*)(smc + K2_WH2);
    float4* st4 = (float4*)(smc + K2_ST4);

    const int tid  = threadIdx.x;
    const int wid  = tid >> 5;
    const int lane = tid & 31;
    const int bt   = blockIdx.x >> 1;
    const int mh   = blockIdx.x & 1;

    const int mt = wid >> 1;
    const int nh = wid & 1;
    const int mrow0 = mt * 32;
    const int ncol0 = nh * 32;
    const int q  = lane & 3;
    const int rw = lane >> 2;

    // ---- B2 fill from global Wh: [256 k][64 n], pitch 72 ----
    {
        const uint4* srcH = (const uint4*)(g_wh_hi + (size_t)bt * N_NODES * 32);
        const uint4* srcL = (const uint4*)(g_wh_lo + (size_t)bt * N_NODES * 32);
        #pragma unroll
        for (int it = 0; it < 8; ++it) {
            int idx = tid + 256 * it;     // 2048 uint4
            int r = idx >> 3, c4 = idx & 7;
            uint4 vh = __ldg(srcH + idx);
            uint4 vl = __ldg(srcL + idx);
            *(uint4*)(smc + K2_B2_HI + r * 144 + c4 * 16) = vh;
            *(uint4*)(smc + K2_B2_LO + r * 144 + c4 * 16) = vl;
        }
        wh2[tid] = g_wh2[(size_t)bt * N_NODES + tid];
    }
    __syncthreads();

    // ---- softmax stats for own 128 rows ----
    for (int i = wid; i < 128; i += 8) {
        const int gi = mh * 128 + i;
        const float s = g_wh1[(size_t)bt * N_NODES + gi];
        const float4* adjrow = (const float4*)(adj + (size_t)gi * N_NODES);
        float4 a0 = __ldg(adjrow + lane * 2);
        float4 a1 = __ldg(adjrow + lane * 2 + 1);
        float4 w0 = *(const float4*)(wh2 + lane * 8);
        float4 w1 = *(const float4*)(wh2 + lane * 8 + 4);
        float ad[8] = {a0.x, a0.y, a0.z, a0.w, a1.x, a1.y, a1.z, a1.w};
        float wv[8] = {w0.x, w0.y, w0.z, w0.w, w1.x, w1.y, w1.z, w1.w};
        float vals[8];
        #pragma unroll
        for (int p = 0; p < 8; ++p) {
            float e = s + wv[p];
            e = e > 0.0f ? e : 0.01f * e;
            vals[p] = (ad[p] > 0.0f) ? e : -3.0e38f;
        }
        float m = vals[0];
        #pragma unroll
        for (int p = 1; p < 8; ++p) m = fmaxf(m, vals[p]);
        #pragma unroll
        for (int off = 16; off > 0; off >>= 1)
            m = fmaxf(m, __shfl_xor_sync(0xffffffffu, m, off));
        float sum = 0.0f;
        #pragma unroll
        for (int p = 0; p < 8; ++p)
            sum += (vals[p] > -1.0e38f) ? __expf(vals[p] - m) : 0.0f;
        #pragma unroll
        for (int off = 16; off > 0; off >>= 1)
            sum += __shfl_xor_sync(0xffffffffu, sum, off);
        if (lane == 0) st4[i] = make_float4(s, m, 1.0f / sum, 0.0f);
    }
    __syncthreads();

    // ---- alpha chunks (4 x [128 m][64 k]) + GEMM2, reg-prefetched ----
    int fr[8], fc4[8];
    #pragma unroll
    for (int it = 0; it < 8; ++it) {
        int idx = tid + 256 * it;     // 2048 float4 per chunk
        fr[it]  = idx >> 4;
        fc4[it] = idx & 15;
    }
    const float* adjB = adj + (size_t)(mh * 128) * N_NODES;
    float4 reg[8];
    // prefill chunk 0
    #pragma unroll
    for (int it = 0; it < 8; ++it)
        reg[it] = __ldg((const float4*)(adjB + (size_t)fr[it] * N_NODES + fc4[it] * 4));
    #pragma unroll
    for (int it = 0; it < 8; ++it) {
        float4 st = st4[fr[it]];
        float4 w = *(const float4*)(wh2 + fc4[it] * 4);
        float4 pv; float e;
        e = st.x + w.x; e = e > 0.f ? e : 0.01f * e; pv.x = (reg[it].x > 0.f) ? __expf(e - st.y) * st.z : 0.f;
        e = st.x + w.y; e = e > 0.f ? e : 0.01f * e; pv.y = (reg[it].y > 0.f) ? __expf(e - st.y) * st.z : 0.f;
        e = st.x + w.z; e = e > 0.f ? e : 0.01f * e; pv.z = (reg[it].z > 0.f) ? __expf(e - st.y) * st.z : 0.f;
        e = st.x + w.w; e = e > 0.f ? e : 0.01f * e; pv.w = (reg[it].w > 0.f) ? __expf(e - st.y) * st.z : 0.f;
        uint2 hi, lo; split4(pv, hi, lo);
        *(uint2*)(smc + K2_A_HI + fr[it] * 144 + fc4[it] * 8) = hi;
        *(uint2*)(smc + K2_A_LO + fr[it] * 144 + fc4[it] * 8) = lo;
    }
    __syncthreads();

    const uint32_t laneRow = (uint32_t)(lane & 15);
    const uint32_t laneCol = (uint32_t)((lane >> 4) * 8);
    const uint32_t aOff = (mrow0 + laneRow) * 144 + laneCol * 2;
    const uint32_t bOff = laneRow * 144 + (ncol0 + laneCol) * 2;

    float acc0[4][4] = {}, acc1[4][4] = {};
    #pragma unroll
    for (int kc = 0; kc < 4; ++kc) {
        if (kc < 3) {
            #pragma unroll
            for (int it = 0; it < 8; ++it)
                reg[it] = __ldg((const float4*)(adjB + (size_t)fr[it] * N_NODES + (kc + 1) * 64 + fc4[it] * 4));
        }
        gemm32<4, 16 * 144, 16 * 144>(acc0, acc1,
            sb + K2_A_HI + aOff, sb + K2_A_LO + aOff,
            sb + K2_B2_HI + (uint32_t)(kc * 64) * 144 + bOff,
            sb + K2_B2_LO + (uint32_t)(kc * 64) * 144 + bOff);
        if (kc < 3) {
            #pragma unroll
            for (int it = 0; it < 8; ++it) {
                float4 st = st4[fr[it]];
                float4 w = *(const float4*)(wh2 + (kc + 1) * 64 + fc4[it] * 4);
                float4 pv; float e;
                e = st.x + w.x; e = e > 0.f ? e : 0.01f * e; pv.x = (reg[it].x > 0.f) ? __expf(e - st.y) * st.z : 0.f;
                e = st.x + w.y; e = e > 0.f ? e : 0.01f * e; pv.y = (reg[it].y > 0.f) ? __expf(e - st.y) * st.z : 0.f;
                e = st.x + w.z; e = e > 0.f ? e : 0.01f * e; pv.z = (reg[it].z > 0.f) ? __expf(e - st.y) * st.z : 0.f;
                e = st.x + w.w; e = e > 0.f ? e : 0.01f * e; pv.w = (reg[it].w > 0.f) ? __expf(e - st.y) * st.z : 0.f;
                reg[it] = pv;
            }
            __syncthreads();
            #pragma unroll
            for (int it = 0; it < 8; ++it) {
                uint2 hi, lo; split4(reg[it], hi, lo);
                *(uint2*)(smc + K2_A_HI + fr[it] * 144 + fc4[it] * 8) = hi;
                *(uint2*)(smc + K2_A_LO + fr[it] * 144 + fc4[it] * 8) = lo;
            }
            __syncthreads();
        }
    }

    // ---- ELU + store ----
    float* outB = out + ((size_t)bt * N_NODES + mh * 128) * F_OUT;
    #pragma unroll
    for (int s = 0; s < 2; ++s) {
        float (*acc)[4] = s ? acc1 : acc0;
        int r0 = mrow0 + 16 * s + rw;
        #pragma unroll
        for (int j = 0; j < 4; ++j) {
            int col = ncol0 + 8 * j + 2 * q;
            float x0 = acc[j][0], x1 = acc[j][1], x2 = acc[j][2], x3 = acc[j][3];
            float2 v0, v1;
            v0.x = x0 > 0.0f ? x0 : expm1f(x0);
            v0.y = x1 > 0.0f ? x1 : expm1f(x1);
            v1.x = x2 > 0.0f ? x2 : expm1f(x2);
            v1.y = x3 > 0.0f ? x3 : expm1f(x3);
            *(float2*)(outB + (size_t)r0 * F_OUT + col)       = v0;
            *(float2*)(outB + (size_t)(r0 + 8) * F_OUT + col) = v1;
        }
    }
}

extern "C" void kernel_launch(void* const* d_in, const int* in_sizes, int n_in,
                              void* d_out, int out_size)
{
    const float* h   = (const float*)d_in[0];   // (8,64,256,128)
    const float* W   = (const float*)d_in[1];   // (128,64)
    const float* a   = (const float*)d_in[2];   // (128,1)
    const float* adj = (const float*)d_in[3];   // (256,256)
    float* out = (float*)d_out;                 // (8,64,256,64)

    cudaFuncSetAttribute(gat_k1, cudaFuncAttributeMaxDynamicSharedMemorySize, K1_TOTAL);
    cudaFuncSetAttribute(gat_k2, cudaFuncAttributeMaxDynamicSharedMemorySize, K2_TOTAL);
    gat_k1<<<BT_TOTAL * 2, 256, K1_TOTAL>>>(h, W, a);
    gat_k2<<<BT_TOTAL * 2, 256, K2_TOTAL>>>(adj, out);
}

// round 13
// speedup vs baseline: 1.0642x; 1.0123x over previous
#include <cuda_runtime.h>
#include <cuda_bf16.h>
#include <stdint.h>
#include <math.h>

#define N_NODES 256
#define F_IN    128
#define F_OUT   64
#define BT_TOTAL 512
#define NTHR    512

// bf16 row pitch 72 elems (144B): 144 mod 128 = 16 -> conflict-free ldmatrix
#define PITCH   72

// ---- smem byte offsets ----
// A chunk block [256 m][64 k] bf16 pitch 72 = 36864 B
#define R_AB0_HI 0
#define R_AB0_LO 36864
#define R_AB1_HI 73728
#define R_AB1_LO 110592
#define R_W_HI   147456                 // W [128 k][64 n] bf16 pitch 72
#define R_W_LO   165888
#define R_B2_HI  R_AB0_HI               // Wh [256 k][64 n] aliases AB0 (dead by epilogue1)
#define R_B2_LO  R_AB0_LO
#define R_SP1    184320                 // [2][256] f32 Wh1 partials
#define R_SP2    186368                 // [2][256] f32 Wh2 partials
#define R_WH1    188416                 // [256] f32
#define R_WH2    189440                 // [256] f32
#define R_ST4    190464                 // [256] float4 (wh1, rmax, rinv, _)
#define R_AV     194560                 // a vector [128] f32
#define SM_TOTAL 195072

static __device__ __forceinline__ uint32_t smem_u32(const void* p) {
    uint32_t a;
    asm("{ .reg .u64 t; cvta.to.shared.u64 t, %1; cvt.u32.u64 %0, t; }" : "=r"(a) : "l"(p));
    return a;
}
static __device__ __forceinline__ void ldsm4(uint32_t& r0, uint32_t& r1, uint32_t& r2, uint32_t& r3, uint32_t addr) {
    asm volatile("ldmatrix.sync.aligned.m8n8.x4.shared.b16 {%0,%1,%2,%3}, [%4];"
                 : "=r"(r0), "=r"(r1), "=r"(r2), "=r"(r3) : "r"(addr));
}
static __device__ __forceinline__ void ldsm4t(uint32_t& r0, uint32_t& r1, uint32_t& r2, uint32_t& r3, uint32_t addr) {
    asm volatile("ldmatrix.sync.aligned.m8n8.x4.trans.shared.b16 {%0,%1,%2,%3}, [%4];"
                 : "=r"(r0), "=r"(r1), "=r"(r2), "=r"(r3) : "r"(addr));
}
static __device__ __forceinline__ void mma16816(float* c,
        uint32_t a0, uint32_t a1, uint32_t a2, uint32_t a3, uint32_t b0, uint32_t b1) {
    asm volatile("mma.sync.aligned.m16n8k16.row.col.f32.bf16.bf16.f32 "
                 "{%0,%1,%2,%3}, {%4,%5,%6,%7}, {%8,%9}, {%0,%1,%2,%3};"
                 : "+f"(c[0]), "+f"(c[1]), "+f"(c[2]), "+f"(c[3])
                 : "r"(a0), "r"(a1), "r"(a2), "r"(a3), "r"(b0), "r"(b1));
}
// packed split: hi word = {bf16(y), bf16(x)}, lo word = residuals
static __device__ __forceinline__ void split2(float x, float y, uint32_t& hi, uint32_t& lo) {
    asm("cvt.rn.bf16x2.f32 %0, %1, %2;" : "=r"(hi) : "f"(y), "f"(x));
    float rx = __uint_as_float(hi << 16);
    float ry = __uint_as_float(hi & 0xFFFF0000u);
    asm("cvt.rn.bf16x2.f32 %0, %1, %2;" : "=r"(lo) : "f"(y - ry), "f"(x - rx));
}
static __device__ __forceinline__ void split4(float4 v, uint2& hi, uint2& lo) {
    split2(v.x, v.y, hi.x, lo.x);
    split2(v.z, v.w, hi.y, lo.y);
}

// 32m x 32n warp GEMM over 64 k (4 ksteps), 3-term bf16 split.
// MMAs issued in ROUNDS across 8 independent accumulator chains so consecutive
// MMAs on the same accumulator are 8 apart (hides HMMA RAW latency in-order).
static __device__ __forceinline__ void gemm_chunk32(
    float (&acc0)[4][4], float (&acc1)[4][4],
    uint32_t aHi, uint32_t aLo, uint32_t bHi, uint32_t bLo)
{
    #pragma unroll
    for (int k0 = 0; k0 < 4; ++k0) {
        const int ka = k0 * 32;
        const int kb = k0 * 16 * (PITCH * 2);
        uint32_t a0h[4], a1h[4], a0l[4], a1l[4], bh[8], bl[8];
        ldsm4(a0h[0], a0h[1], a0h[2], a0h[3], aHi + ka);
        ldsm4(a1h[0], a1h[1], a1h[2], a1h[3], aHi + 16 * (PITCH * 2) + ka);
        ldsm4(a0l[0], a0l[1], a0l[2], a0l[3], aLo + ka);
        ldsm4(a1l[0], a1l[1], a1l[2], a1l[3], aLo + 16 * (PITCH * 2) + ka);
        ldsm4t(bh[0], bh[1], bh[2], bh[3], bHi + kb);
        ldsm4t(bh[4], bh[5], bh[6], bh[7], bHi + kb + 32);
        ldsm4t(bl[0], bl[1], bl[2], bl[3], bLo + kb);
        ldsm4t(bl[4], bl[5], bl[6], bl[7], bLo + kb + 32);
        // round 1: Ahi * Bhi  (8 independent MMAs)
        #pragma unroll
        for (int j = 0; j < 4; ++j)
            mma16816(acc0[j], a0h[0], a0h[1], a0h[2], a0h[3], bh[2*j], bh[2*j+1]);
        #pragma unroll
        for (int j = 0; j < 4; ++j)
            mma16816(acc1[j], a1h[0], a1h[1], a1h[2], a1h[3], bh[2*j], bh[2*j+1]);
        // round 2: Ahi * Blo
        #pragma unroll
        for (int j = 0; j < 4; ++j)
            mma16816(acc0[j], a0h[0], a0h[1], a0h[2], a0h[3], bl[2*j], bl[2*j+1]);
        #pragma unroll
        for (int j = 0; j < 4; ++j)
            mma16816(acc1[j], a1h[0], a1h[1], a1h[2], a1h[3], bl[2*j], bl[2*j+1]);
        // round 3: Alo * Bhi
        #pragma unroll
        for (int j = 0; j < 4; ++j)
            mma16816(acc0[j], a0l[0], a0l[1], a0l[2], a0l[3], bh[2*j], bh[2*j+1]);
        #pragma unroll
        for (int j = 0; j < 4; ++j)
            mma16816(acc1[j], a1l[0], a1l[1], a1l[2], a1l[3], bh[2*j], bh[2*j+1]);
    }
}

__global__ __launch_bounds__(NTHR, 1)
void gat_mma_kernel(const float* __restrict__ h,
                    const float* __restrict__ W,
                    const float* __restrict__ a,
                    const float* __restrict__ adj,
                    float* __restrict__ out)
{
    extern __shared__ char smc[];
    const uint32_t sb = smem_u32(smc);
    float*  sP1 = (float*)(smc + R_SP1);
    float*  sP2 = (float*)(smc + R_SP2);
    float*  wh1 = (float*)(smc + R_WH1);
    float*  wh2 = (float*)(smc + R_WH2);
    float4* st4 = (float4*)(smc + R_ST4);
    float*  sav = (float*)(smc + R_AV);

    const int tid  = threadIdx.x;
    const int wid  = tid >> 5;
    const int lane = tid & 31;
    const int bt   = blockIdx.x;

    const int mt = wid >> 1;           // m-tile 0..7 (32 rows)
    const int nh = wid & 1;            // n-half 0..1 (32 cols)
    const int mrow0 = mt * 32;
    const int ncol0 = nh * 32;
    const int q  = lane & 3;
    const int rw = lane >> 2;

    const float* hB = h + (size_t)bt * N_NODES * F_IN;

    const uint32_t laneRow = (uint32_t)(lane & 15);
    const uint32_t laneCol = (uint32_t)((lane >> 4) * 8);
    const uint32_t aOff = ((mrow0 + laneRow) * PITCH + laneCol) * 2;
    const uint32_t bOff = (laneRow * PITCH + ncol0 + laneCol) * 2;

    // chunk fill index decomposition: 4096 float4 per [256][64] chunk, 8/thread
    int fr[8], fc4[8];
    #pragma unroll
    for (int it = 0; it < 8; ++it) {
        int idx = tid + NTHR * it;
        fr[it]  = idx >> 4;      // row 0..255
        fc4[it] = idx & 15;      // float4-col 0..15
    }

    // ================= fills: W, h kc0 -> AB0, h kc1 -> AB1, a =================
    {
        #pragma unroll
        for (int it = 0; it < 4; ++it) {
            int idx = tid + NTHR * it;
            int r = idx >> 4, c4 = idx & 15;
            float4 v = *(const float4*)(W + r * F_OUT + c4 * 4);
            uint2 hi, lo; split4(v, hi, lo);
            *(uint2*)(smc + R_W_HI + (r * PITCH + c4 * 4) * 2) = hi;
            *(uint2*)(smc + R_W_LO + (r * PITCH + c4 * 4) * 2) = lo;
        }
        float4 v0[8], v1[8];
        #pragma unroll
        for (int it = 0; it < 8; ++it)
            v0[it] = *(const float4*)(hB + (size_t)fr[it] * F_IN + fc4[it] * 4);
        #pragma unroll
        for (int it = 0; it < 8; ++it)
            v1[it] = *(const float4*)(hB + (size_t)fr[it] * F_IN + 64 + fc4[it] * 4);
        #pragma unroll
        for (int it = 0; it < 8; ++it) {
            int off = (fr[it] * PITCH + fc4[it] * 4) * 2;
            uint2 hi, lo;
            split4(v0[it], hi, lo);
            *(uint2*)(smc + R_AB0_HI + off) = hi;
            *(uint2*)(smc + R_AB0_LO + off) = lo;
            split4(v1[it], hi, lo);
            *(uint2*)(smc + R_AB1_HI + off) = hi;
            *(uint2*)(smc + R_AB1_LO + off) = lo;
        }
        if (tid < 128) sav[tid] = a[tid];
    }
    __syncthreads();

    // ================= GEMM1: Wh = h @ W (full 256m x 64n x 128k) =================
    {
        float acc0[4][4] = {}, acc1[4][4] = {};
        gemm_chunk32(acc0, acc1, sb + R_AB0_HI + aOff, sb + R_AB0_LO + aOff,
                     sb + R_W_HI + bOff, sb + R_W_LO + bOff);
        gemm_chunk32(acc0, acc1, sb + R_AB1_HI + aOff, sb + R_AB1_LO + aOff,
                     sb + R_W_HI + 64 * (PITCH * 2) + bOff,
                     sb + R_W_LO + 64 * (PITCH * 2) + bOff);

        // ---- epilogue1: Wh1/Wh2 partials + Wh -> split bf16 into B2 (=AB0) ----
        float p1l[2] = {0.f, 0.f}, p1h[2] = {0.f, 0.f};
        float p2l[2] = {0.f, 0.f}, p2h[2] = {0.f, 0.f};
        #pragma unroll
        for (int s = 0; s < 2; ++s) {
            float (*acc)[4] = s ? acc1 : acc0;
            #pragma unroll
            for (int j = 0; j < 4; ++j) {
                int col = ncol0 + 8 * j + 2 * q;
                float a10 = sav[col], a11 = sav[col + 1];
                float a20 = sav[64 + col], a21 = sav[64 + col + 1];
                p1l[s] += acc[j][0] * a10 + acc[j][1] * a11;
                p1h[s] += acc[j][2] * a10 + acc[j][3] * a11;
                p2l[s] += acc[j][0] * a20 + acc[j][1] * a21;
                p2h[s] += acc[j][2] * a20 + acc[j][3] * a21;
            }
        }
        #pragma unroll
        for (int off = 1; off <= 2; off <<= 1) {
            #pragma unroll
            for (int s = 0; s < 2; ++s) {
                p1l[s] += __shfl_xor_sync(0xffffffffu, p1l[s], off);
                p1h[s] += __shfl_xor_sync(0xffffffffu, p1h[s], off);
                p2l[s] += __shfl_xor_sync(0xffffffffu, p2l[s], off);
                p2h[s] += __shfl_xor_sync(0xffffffffu, p2h[s], off);
            }
        }
        if (q == 0) {
            #pragma unroll
            for (int s = 0; s < 2; ++s) {
                int r0 = mrow0 + 16 * s + rw;
                sP1[nh * 256 + r0]     = p1l[s];
                sP1[nh * 256 + r0 + 8] = p1h[s];
                sP2[nh * 256 + r0]     = p2l[s];
                sP2[nh * 256 + r0 + 8] = p2h[s];
            }
        }
        #pragma unroll
        for (int s = 0; s < 2; ++s) {
            float (*acc)[4] = s ? acc1 : acc0;
            int r0 = mrow0 + 16 * s + rw;
            #pragma unroll
            for (int j = 0; j < 4; ++j) {
                int col = ncol0 + 8 * j + 2 * q;
                uint32_t hi, lo;
                split2(acc[j][0], acc[j][1], hi, lo);
                *(uint32_t*)(smc + R_B2_HI + (r0 * PITCH + col) * 2) = hi;
                *(uint32_t*)(smc + R_B2_LO + (r0 * PITCH + col) * 2) = lo;
                split2(acc[j][2], acc[j][3], hi, lo);
                *(uint32_t*)(smc + R_B2_HI + ((r0 + 8) * PITCH + col) * 2) = hi;
                *(uint32_t*)(smc + R_B2_LO + ((r0 + 8) * PITCH + col) * 2) = lo;
            }
        }
    }
    __syncthreads();

    // ---- combine Wh1/Wh2 partials ----
    if (tid < 256) {
        wh1[tid] = sP1[tid] + sP1[256 + tid];
        wh2[tid] = sP2[tid] + sP2[256 + tid];
    }
    __syncthreads();

    // ================= Phase 2: softmax stats =================
    for (int i = wid; i < N_NODES; i += 16) {
        const float s = wh1[i];
        const float4* adjrow = (const float4*)(adj + (size_t)i * N_NODES);
        float4 a0 = __ldg(adjrow + lane * 2);
        float4 a1 = __ldg(adjrow + lane * 2 + 1);
        float4 w0 = *(const float4*)(wh2 + lane * 8);
        float4 w1 = *(const float4*)(wh2 + lane * 8 + 4);
        float ad[8] = {a0.x, a0.y, a0.z, a0.w, a1.x, a1.y, a1.z, a1.w};
        float wv[8] = {w0.x, w0.y, w0.z, w0.w, w1.x, w1.y, w1.z, w1.w};
        float vals[8];
        #pragma unroll
        for (int p = 0; p < 8; ++p) {
            float e = s + wv[p];
            e = e > 0.0f ? e : 0.01f * e;
            vals[p] = (ad[p] > 0.0f) ? e : -3.0e38f;
        }
        float m = vals[0];
        #pragma unroll
        for (int p = 1; p < 8; ++p) m = fmaxf(m, vals[p]);
        #pragma unroll
        for (int off = 16; off > 0; off >>= 1)
            m = fmaxf(m, __shfl_xor_sync(0xffffffffu, m, off));
        float sum = 0.0f;
        #pragma unroll
        for (int p = 0; p < 8; ++p)
            sum += (vals[p] > -1.0e38f) ? __expf(vals[p] - m) : 0.0f;
        #pragma unroll
        for (int off = 16; off > 0; off >>= 1)
            sum += __shfl_xor_sync(0xffffffffu, sum, off);
        if (lane == 0) st4[i] = make_float4(s, m, 1.0f / sum, 0.0f);
    }
    __syncthreads();

    // ================= Phase 3: h' = alpha @ Wh (4 x 64k chunks in AB1) =================
    float* outB = out + (size_t)bt * N_NODES * F_OUT;
    float4 reg[8];
    // prefill chunk 0
    #pragma unroll
    for (int it = 0; it < 8; ++it)
        reg[it] = __ldg((const float4*)(adj + (size_t)fr[it] * N_NODES + fc4[it] * 4));
    #pragma unroll
    for (int it = 0; it < 8; ++it) {
        float4 st = st4[fr[it]];
        float4 w = *(const float4*)(wh2 + fc4[it] * 4);
        float4 pv; float e;
        e = st.x + w.x; e = e > 0.f ? e : 0.01f * e; pv.x = (reg[it].x > 0.f) ? __expf(e - st.y) * st.z : 0.f;
        e = st.x + w.y; e = e > 0.f ? e : 0.01f * e; pv.y = (reg[it].y > 0.f) ? __expf(e - st.y) * st.z : 0.f;
        e = st.x + w.z; e = e > 0.f ? e : 0.01f * e; pv.z = (reg[it].z > 0.f) ? __expf(e - st.y) * st.z : 0.f;
        e = st.x + w.w; e = e > 0.f ? e : 0.01f * e; pv.w = (reg[it].w > 0.f) ? __expf(e - st.y) * st.z : 0.f;
        int off = (fr[it] * PITCH + fc4[it] * 4) * 2;
        uint2 hi, lo; split4(pv, hi, lo);
        *(uint2*)(smc + R_AB1_HI + off) = hi;
        *(uint2*)(smc + R_AB1_LO + off) = lo;
    }
    __syncthreads();

    float acc0[4][4] = {}, acc1[4][4] = {};
    #pragma unroll
    for (int kc = 0; kc < 4; ++kc) {
        if (kc < 3) {
            #pragma unroll
            for (int it = 0; it < 8; ++it)
                reg[it] = __ldg((const float4*)(adj + (size_t)fr[it] * N_NODES + (kc + 1) * 64 + fc4[it] * 4));
        }
        gemm_chunk32(acc0, acc1, sb + R_AB1_HI + aOff, sb + R_AB1_LO + aOff,
                     sb + R_B2_HI + (uint32_t)(kc * 64) * (PITCH * 2) + bOff,
                     sb + R_B2_LO + (uint32_t)(kc * 64) * (PITCH * 2) + bOff);
        if (kc < 3) {
            // exp transform in regs (before barrier: overlaps warp skew)
            #pragma unroll
            for (int it = 0; it < 8; ++it) {
                float4 st = st4[fr[it]];
                float4 w = *(const float4*)(wh2 + (kc + 1) * 64 + fc4[it] * 4);
                float4 pv; float e;
                e = st.x + w.x; e = e > 0.f ? e : 0.01f * e; pv.x = (reg[it].x > 0.f) ? __expf(e - st.y) * st.z : 0.f;
                e = st.x + w.y; e = e > 0.f ? e : 0.01f * e; pv.y = (reg[it].y > 0.f) ? __expf(e - st.y) * st.z : 0.f;
                e = st.x + w.z; e = e > 0.f ? e : 0.01f * e; pv.z = (reg[it].z > 0.f) ? __expf(e - st.y) * st.z : 0.f;
                e = st.x + w.w; e = e > 0.f ? e : 0.01f * e; pv.w = (reg[it].w > 0.f) ? __expf(e - st.y) * st.z : 0.f;
                reg[it] = pv;
            }
            __syncthreads();    // all reads of AB1 (chunk kc) done
            #pragma unroll
            for (int it = 0; it < 8; ++it) {
                int off = (fr[it] * PITCH + fc4[it] * 4) * 2;
                uint2 hi, lo; split4(reg[it], hi, lo);
                *(uint2*)(smc + R_AB1_HI + off) = hi;
                *(uint2*)(smc + R_AB1_LO + off) = lo;
            }
            __syncthreads();    // chunk kc+1 visible
        }
    }

    // ---- epilogue2: ELU + store ----
    #pragma unroll
    for (int s = 0; s < 2; ++s) {
        float (*acc)[4] = s ? acc1 : acc0;
        int r0 = mrow0 + 16 * s + rw;
        #pragma unroll
        for (int j = 0; j < 4; ++j) {
            int col = ncol0 + 8 * j + 2 * q;
            float x0 = acc[j][0], x1 = acc[j][1], x2 = acc[j][2], x3 = acc[j][3];
            float2 v0, v1;
            v0.x = x0 > 0.0f ? x0 : expm1f(x0);
            v0.y = x1 > 0.0f ? x1 : expm1f(x1);
            v1.x = x2 > 0.0f ? x2 : expm1f(x2);
            v1.y = x3 > 0.0f ? x3 : expm1f(x3);
            *(float2*)(outB + (size_t)r0 * F_OUT + col)       = v0;
            *(float2*)(outB + (size_t)(r0 + 8) * F_OUT + col) = v1;
        }
    }
}

extern "C" void kernel_launch(void* const* d_in, const int* in_sizes, int n_in,
                              void* d_out, int out_size)
{
    const float* h   = (const float*)d_in[0];   // (8,64,256,128)
    const float* W   = (const float*)d_in[1];   // (128,64)
    const float* a   = (const float*)d_in[2];   // (128,1)
    const float* adj = (const float*)d_in[3];   // (256,256)
    float* out = (float*)d_out;                 // (8,64,256,64)

    cudaFuncSetAttribute(gat_mma_kernel,
                         cudaFuncAttributeMaxDynamicSharedMemorySize, SM_TOTAL);
    gat_mma_kernel<<<BT_TOTAL, NTHR, SM_TOTAL>>>(h, W, a, adj, out);
}

// round 17
// speedup vs baseline: 1.1732x; 1.1024x over previous
#include <cuda_runtime.h>
#include <cuda_bf16.h>
#include <stdint.h>
#include <math.h>

#define N_NODES 256
#define F_IN    128
#define F_OUT   64
#define BT_TOTAL 512
#define NTHR    512

// bf16 row pitch 72 elems (144B): 144 mod 128 = 16 -> conflict-free ldmatrix
#define PITCH   72

// ---- smem byte offsets ----
#define R_AB0_HI 0
#define R_AB0_LO 36864
#define R_AB1_HI 73728
#define R_AB1_LO 110592
#define R_W_HI   147456                 // W [128 k][64 n] bf16 pitch 72
#define R_W_LO   165888
#define R_B2_HI  R_AB0_HI               // Wh [256 k][64 n] aliases AB0 (dead by epilogue1)
#define R_B2_LO  R_AB0_LO
#define R_SP1    184320                 // [2][256] f32 Wh1 partials
#define R_SP2    186368                 // [2][256] f32 Wh2 partials
#define R_WH1    188416                 // [256] f32
#define R_WH2    189440                 // [256] f32
#define R_ST4    190464                 // [256] float4 (wh1, rmax, rinv, _)
#define R_AV     194560                 // a vector [128] f32
#define SM_TOTAL 195072

static __device__ __forceinline__ uint32_t smem_u32(const void* p) {
    uint32_t a;
    asm("{ .reg .u64 t; cvta.to.shared.u64 t, %1; cvt.u32.u64 %0, t; }" : "=r"(a) : "l"(p));
    return a;
}
static __device__ __forceinline__ void ldsm4(uint32_t& r0, uint32_t& r1, uint32_t& r2, uint32_t& r3, uint32_t addr) {
    asm volatile("ldmatrix.sync.aligned.m8n8.x4.shared.b16 {%0,%1,%2,%3}, [%4];"
                 : "=r"(r0), "=r"(r1), "=r"(r2), "=r"(r3) : "r"(addr));
}
static __device__ __forceinline__ void ldsm4t(uint32_t& r0, uint32_t& r1, uint32_t& r2, uint32_t& r3, uint32_t addr) {
    asm volatile("ldmatrix.sync.aligned.m8n8.x4.trans.shared.b16 {%0,%1,%2,%3}, [%4];"
                 : "=r"(r0), "=r"(r1), "=r"(r2), "=r"(r3) : "r"(addr));
}
static __device__ __forceinline__ void mma16816(float* c,
        uint32_t a0, uint32_t a1, uint32_t a2, uint32_t a3, uint32_t b0, uint32_t b1) {
    asm volatile("mma.sync.aligned.m16n8k16.row.col.f32.bf16.bf16.f32 "
                 "{%0,%1,%2,%3}, {%4,%5,%6,%7}, {%8,%9}, {%0,%1,%2,%3};"
                 : "+f"(c[0]), "+f"(c[1]), "+f"(c[2]), "+f"(c[3])
                 : "r"(a0), "r"(a1), "r"(a2), "r"(a3), "r"(b0), "r"(b1));
}
// packed split: hi word = {bf16(y), bf16(x)}, lo word = residuals
static __device__ __forceinline__ void split2(float x, float y, uint32_t& hi, uint32_t& lo) {
    asm("cvt.rn.bf16x2.f32 %0, %1, %2;" : "=r"(hi) : "f"(y), "f"(x));
    float rx = __uint_as_float(hi << 16);
    float ry = __uint_as_float(hi & 0xFFFF0000u);
    asm("cvt.rn.bf16x2.f32 %0, %1, %2;" : "=r"(lo) : "f"(y - ry), "f"(x - rx));
}
static __device__ __forceinline__ void split4(float4 v, uint2& hi, uint2& lo) {
    split2(v.x, v.y, hi.x, lo.x);
    split2(v.z, v.w, hi.y, lo.y);
}
// alpha element: st = (wh1, rmax, rinv, _)
static __device__ __forceinline__ float alpha1(float4 st, float w, float ad) {
    float e = st.x + w;
    e = fmaxf(e, 0.01f * e);
    float p = __expf(e - st.y) * st.z;
    return ad > 0.f ? p : 0.f;
}

// 32m x 32n warp GEMM over 64 k (4 ksteps), 3-term bf16 split (GEMM1 only)
static __device__ __forceinline__ void gemm_chunk32(
    float (&acc0)[4][4], float (&acc1)[4][4],
    uint32_t aHi, uint32_t aLo, uint32_t bHi, uint32_t bLo)
{
    #pragma unroll
    for (int k0 = 0; k0 < 4; ++k0) {
        const int ka = k0 * 32;
        const int kb = k0 * 16 * (PITCH * 2);
        uint32_t a0h[4], a1h[4], a0l[4], a1l[4], bh[8], bl[8];
        ldsm4(a0h[0], a0h[1], a0h[2], a0h[3], aHi + ka);
        ldsm4(a1h[0], a1h[1], a1h[2], a1h[3], aHi + 16 * (PITCH * 2) + ka);
        ldsm4(a0l[0], a0l[1], a0l[2], a0l[3], aLo + ka);
        ldsm4(a1l[0], a1l[1], a1l[2], a1l[3], aLo + 16 * (PITCH * 2) + ka);
        ldsm4t(bh[0], bh[1], bh[2], bh[3], bHi + kb);
        ldsm4t(bh[4], bh[5], bh[6], bh[7], bHi + kb + 32);
        ldsm4t(bl[0], bl[1], bl[2], bl[3], bLo + kb);
        ldsm4t(bl[4], bl[5], bl[6], bl[7], bLo + kb + 32);
        #pragma unroll
        for (int j = 0; j < 4; ++j)
            mma16816(acc0[j], a0h[0], a0h[1], a0h[2], a0h[3], bh[2*j], bh[2*j+1]);
        #pragma unroll
        for (int j = 0; j < 4; ++j)
            mma16816(acc1[j], a1h[0], a1h[1], a1h[2], a1h[3], bh[2*j], bh[2*j+1]);
        #pragma unroll
        for (int j = 0; j < 4; ++j)
            mma16816(acc0[j], a0h[0], a0h[1], a0h[2], a0h[3], bl[2*j], bl[2*j+1]);
        #pragma unroll
        for (int j = 0; j < 4; ++j)
            mma16816(acc1[j], a1h[0], a1h[1], a1h[2], a1h[3], bl[2*j], bl[2*j+1]);
        #pragma unroll
        for (int j = 0; j < 4; ++j)
            mma16816(acc0[j], a0l[0], a0l[1], a0l[2], a0l[3], bh[2*j], bh[2*j+1]);
        #pragma unroll
        for (int j = 0; j < 4; ++j)
            mma16816(acc1[j], a1l[0], a1l[1], a1l[2], a1l[3], bh[2*j], bh[2*j+1]);
    }
}

__global__ __launch_bounds__(NTHR, 1)
void gat_mma_kernel(const float* __restrict__ h,
                    const float* __restrict__ W,
                    const float* __restrict__ a,
                    const float* __restrict__ adj,
                    float* __restrict__ out)
{
    extern __shared__ char smc[];
    const uint32_t sb = smem_u32(smc);
    float*  sP1 = (float*)(smc + R_SP1);
    float*  sP2 = (float*)(smc + R_SP2);
    float*  wh1 = (float*)(smc + R_WH1);
    float*  wh2 = (float*)(smc + R_WH2);
    float4* st4 = (float4*)(smc + R_ST4);
    float*  sav = (float*)(smc + R_AV);

    const int tid  = threadIdx.x;
    const int wid  = tid >> 5;
    const int lane = tid & 31;
    const int bt   = blockIdx.x;

    const int mt = wid >> 1;           // GEMM1: m-tile 0..7 (32 rows)
    const int nh = wid & 1;            // GEMM1: n-half
    const int mrow0 = mt * 32;
    const int ncol0 = nh * 32;
    const int q  = lane & 3;
    const int rw = lane >> 2;

    const float* hB = h + (size_t)bt * N_NODES * F_IN;

    const uint32_t laneRow = (uint32_t)(lane & 15);
    const uint32_t laneCol = (uint32_t)((lane >> 4) * 8);
    const uint32_t aOff = ((mrow0 + laneRow) * PITCH + laneCol) * 2;
    const uint32_t bOff = (laneRow * PITCH + ncol0 + laneCol) * 2;

    // GEMM1 fill decomposition: 4096 float4 per [256][64] chunk
    int fr[8], fc4[8];
    #pragma unroll
    for (int it = 0; it < 8; ++it) {
        int idx = tid + NTHR * it;
        fr[it]  = idx >> 4;
        fc4[it] = idx & 15;
    }

    // ================= fills: W, h kc0 -> AB0, h kc1 -> AB1, a =================
    {
        #pragma unroll
        for (int it = 0; it < 4; ++it) {
            int idx = tid + NTHR * it;
            int r = idx >> 4, c4 = idx & 15;
            float4 v = *(const float4*)(W + r * F_OUT + c4 * 4);
            uint2 hi, lo; split4(v, hi, lo);
            *(uint2*)(smc + R_W_HI + (r * PITCH + c4 * 4) * 2) = hi;
            *(uint2*)(smc + R_W_LO + (r * PITCH + c4 * 4) * 2) = lo;
        }
        float4 v0[8], v1[8];
        #pragma unroll
        for (int it = 0; it < 8; ++it)
            v0[it] = *(const float4*)(hB + (size_t)fr[it] * F_IN + fc4[it] * 4);
        #pragma unroll
        for (int it = 0; it < 8; ++it)
            v1[it] = *(const float4*)(hB + (size_t)fr[it] * F_IN + 64 + fc4[it] * 4);
        #pragma unroll
        for (int it = 0; it < 8; ++it) {
            int off = (fr[it] * PITCH + fc4[it] * 4) * 2;
            uint2 hi, lo;
            split4(v0[it], hi, lo);
            *(uint2*)(smc + R_AB0_HI + off) = hi;
            *(uint2*)(smc + R_AB0_LO + off) = lo;
            split4(v1[it], hi, lo);
            *(uint2*)(smc + R_AB1_HI + off) = hi;
            *(uint2*)(smc + R_AB1_LO + off) = lo;
        }
        if (tid < 128) sav[tid] = a[tid];
    }
    __syncthreads();

    // ================= GEMM1: Wh = h @ W (full 256m x 64n x 128k) =================
    {
        float acc0[4][4] = {}, acc1[4][4] = {};
        gemm_chunk32(acc0, acc1, sb + R_AB0_HI + aOff, sb + R_AB0_LO + aOff,
                     sb + R_W_HI + bOff, sb + R_W_LO + bOff);
        gemm_chunk32(acc0, acc1, sb + R_AB1_HI + aOff, sb + R_AB1_LO + aOff,
                     sb + R_W_HI + 64 * (PITCH * 2) + bOff,
                     sb + R_W_LO + 64 * (PITCH * 2) + bOff);

        // ---- epilogue1: Wh1/Wh2 partials + Wh -> split bf16 into B2 (=AB0) ----
        float p1l[2] = {0.f, 0.f}, p1h[2] = {0.f, 0.f};
        float p2l[2] = {0.f, 0.f}, p2h[2] = {0.f, 0.f};
        #pragma unroll
        for (int s = 0; s < 2; ++s) {
            float (*acc)[4] = s ? acc1 : acc0;
            #pragma unroll
            for (int j = 0; j < 4; ++j) {
                int col = ncol0 + 8 * j + 2 * q;
                float a10 = sav[col], a11 = sav[col + 1];
                float a20 = sav[64 + col], a21 = sav[64 + col + 1];
                p1l[s] += acc[j][0] * a10 + acc[j][1] * a11;
                p1h[s] += acc[j][2] * a10 + acc[j][3] * a11;
                p2l[s] += acc[j][0] * a20 + acc[j][1] * a21;
                p2h[s] += acc[j][2] * a20 + acc[j][3] * a21;
            }
        }
        #pragma unroll
        for (int off = 1; off <= 2; off <<= 1) {
            #pragma unroll
            for (int s = 0; s < 2; ++s) {
                p1l[s] += __shfl_xor_sync(0xffffffffu, p1l[s], off);
                p1h[s] += __shfl_xor_sync(0xffffffffu, p1h[s], off);
                p2l[s] += __shfl_xor_sync(0xffffffffu, p2l[s], off);
                p2h[s] += __shfl_xor_sync(0xffffffffu, p2h[s], off);
            }
        }
        if (q == 0) {
            #pragma unroll
            for (int s = 0; s < 2; ++s) {
                int r0 = mrow0 + 16 * s + rw;
                sP1[nh * 256 + r0]     = p1l[s];
                sP1[nh * 256 + r0 + 8] = p1h[s];
                sP2[nh * 256 + r0]     = p2l[s];
                sP2[nh * 256 + r0 + 8] = p2h[s];
            }
        }
        #pragma unroll
        for (int s = 0; s < 2; ++s) {
            float (*acc)[4] = s ? acc1 : acc0;
            int r0 = mrow0 + 16 * s + rw;
            #pragma unroll
            for (int j = 0; j < 4; ++j) {
                int col = ncol0 + 8 * j + 2 * q;
                uint32_t hi, lo;
                split2(acc[j][0], acc[j][1], hi, lo);
                *(uint32_t*)(smc + R_B2_HI + (r0 * PITCH + col) * 2) = hi;
                *(uint32_t*)(smc + R_B2_LO + (r0 * PITCH + col) * 2) = lo;
                split2(acc[j][2], acc[j][3], hi, lo);
                *(uint32_t*)(smc + R_B2_HI + ((r0 + 8) * PITCH + col) * 2) = hi;
                *(uint32_t*)(smc + R_B2_LO + ((r0 + 8) * PITCH + col) * 2) = lo;
            }
        }
    }
    __syncthreads();

    // ---- combine Wh1/Wh2 partials ----
    if (tid < 256) {
        wh1[tid] = sP1[tid] + sP1[256 + tid];
        wh2[tid] = sP2[tid] + sP2[256 + tid];
    }
    __syncthreads();

    // ================= Phase 2: softmax stats =================
    for (int i = wid; i < N_NODES; i += 16) {
        const float s = wh1[i];
        const float4* adjrow = (const float4*)(adj + (size_t)i * N_NODES);
        float4 a0 = __ldg(adjrow + lane * 2);
        float4 a1 = __ldg(adjrow + lane * 2 + 1);
        float4 w0 = *(const float4*)(wh2 + lane * 8);
        float4 w1 = *(const float4*)(wh2 + lane * 8 + 4);
        float ad[8] = {a0.x, a0.y, a0.z, a0.w, a1.x, a1.y, a1.z, a1.w};
        float wv[8] = {w0.x, w0.y, w0.z, w0.w, w1.x, w1.y, w1.z, w1.w};
        float vals[8];
        #pragma unroll
        for (int p = 0; p < 8; ++p) {
            float e = s + wv[p];
            e = e > 0.0f ? e : 0.01f * e;
            vals[p] = (ad[p] > 0.0f) ? e : -3.0e38f;
        }
        float m = vals[0];
        #pragma unroll
        for (int p = 1; p < 8; ++p) m = fmaxf(m, vals[p]);
        #pragma unroll
        for (int off = 16; off > 0; off >>= 1)
            m = fmaxf(m, __shfl_xor_sync(0xffffffffu, m, off));
        float sum = 0.0f;
        #pragma unroll
        for (int p = 0; p < 8; ++p)
            sum += (vals[p] > -1.0e38f) ? __expf(vals[p] - m) : 0.0f;
        #pragma unroll
        for (int off = 16; off > 0; off >>= 1)
            sum += __shfl_xor_sync(0xffffffffu, sum, off);
        if (lane == 0) st4[i] = make_float4(s, m, 1.0f / sum, 0.0f);
    }
    __syncthreads();   // st4, wh2, B2 all visible -> phase 3 is barrier-free

    // ======== Phase 3: register-direct alpha GEMM2 (16 warps x 16m x 64n) ========
    {
        const int r   = lane >> 2;          // 0..7
        const int cq  = (lane & 3) * 2;     // 0,2,4,6
        const int rowA = wid * 16 + r;
        const int rowB = rowA + 8;
        const float4 stA = st4[rowA];
        const float4 stB = st4[rowB];
        const float* adjA = adj + (size_t)rowA * N_NODES;
        const float* adjB = adj + (size_t)rowB * N_NODES;

        // B2 per-lane ldsm base (cols 0 + laneCol); col groups at +0,+32,+64,+96 B
        const uint32_t bHiB = sb + R_B2_HI + (laneRow * PITCH + laneCol) * 2;
        const uint32_t bLoB = sb + R_B2_LO + (laneRow * PITCH + laneCol) * 2;

        float acc[8][4] = {};

        // prefetch kstep 0 adj
        float2 ad0A = __ldg((const float2*)(adjA + cq));
        float2 ad1A = __ldg((const float2*)(adjA + cq + 8));
        float2 ad0B = __ldg((const float2*)(adjB + cq));
        float2 ad1B = __ldg((const float2*)(adjB + cq + 8));

        #pragma unroll 4
        for (int ks = 0; ks < 16; ++ks) {
            const int kc = ks * 16;
            float2 w0 = *(const float2*)(wh2 + kc + cq);
            float2 w1 = *(const float2*)(wh2 + kc + cq + 8);

            // alphas -> A fragments
            float pA0x = alpha1(stA, w0.x, ad0A.x), pA0y = alpha1(stA, w0.y, ad0A.y);
            float pB0x = alpha1(stB, w0.x, ad0B.x), pB0y = alpha1(stB, w0.y, ad0B.y);
            float pA1x = alpha1(stA, w1.x, ad1A.x), pA1y = alpha1(stA, w1.y, ad1A.y);
            float pB1x = alpha1(stB, w1.x, ad1B.x), pB1y = alpha1(stB, w1.y, ad1B.y);

            // prefetch next kstep adj (hides L2 latency under MMAs)
            if (ks < 15) {
                ad0A = __ldg((const float2*)(adjA + kc + 16 + cq));
                ad1A = __ldg((const float2*)(adjA + kc + 16 + cq + 8));
                ad0B = __ldg((const float2*)(adjB + kc + 16 + cq));
                ad1B = __ldg((const float2*)(adjB + kc + 16 + cq + 8));
            }

            uint32_t a0h, a0l, a1h, a1l, a2h, a2l, a3h, a3l;
            split2(pA0x, pA0y, a0h, a0l);
            split2(pB0x, pB0y, a1h, a1l);
            split2(pA1x, pA1y, a2h, a2l);
            split2(pB1x, pB1y, a3h, a3l);

            // B fragments: 64 cols x 16 k
            const uint32_t kb = (uint32_t)kc * (PITCH * 2);
            uint32_t bh[16], bl[16];
            ldsm4t(bh[0],  bh[1],  bh[2],  bh[3],  bHiB + kb);
            ldsm4t(bh[4],  bh[5],  bh[6],  bh[7],  bHiB + kb + 32);
            ldsm4t(bh[8],  bh[9],  bh[10], bh[11], bHiB + kb + 64);
            ldsm4t(bh[12], bh[13], bh[14], bh[15], bHiB + kb + 96);
            ldsm4t(bl[0],  bl[1],  bl[2],  bl[3],  bLoB + kb);
            ldsm4t(bl[4],  bl[5],  bl[6],  bl[7],  bLoB + kb + 32);
            ldsm4t(bl[8],  bl[9],  bl[10], bl[11], bLoB + kb + 64);
            ldsm4t(bl[12], bl[13], bl[14], bl[15], bLoB + kb + 96);

            #pragma unroll
            for (int j = 0; j < 8; ++j)
                mma16816(acc[j], a0h, a1h, a2h, a3h, bh[2*j], bh[2*j+1]);
            #pragma unroll
            for (int j = 0; j < 8; ++j)
                mma16816(acc[j], a0h, a1h, a2h, a3h, bl[2*j], bl[2*j+1]);
            #pragma unroll
            for (int j = 0; j < 8; ++j)
                mma16816(acc[j], a0l, a1l, a2l, a3l, bh[2*j], bh[2*j+1]);
        }

        // ---- epilogue2: ELU + store ----
        float* outB = out + (size_t)bt * N_NODES * F_OUT;
        #pragma unroll
        for (int j = 0; j < 8; ++j) {
            int col = j * 8 + cq;
            float x0 = acc[j][0], x1 = acc[j][1], x2 = acc[j][2], x3 = acc[j][3];
            float2 vA, vB;
            vA.x = x0 > 0.0f ? x0 : expm1f(x0);
            vA.y = x1 > 0.0f ? x1 : expm1f(x1);
            vB.x = x2 > 0.0f ? x2 : expm1f(x2);
            vB.y = x3 > 0.0f ? x3 : expm1f(x3);
            *(float2*)(outB + (size_t)rowA * F_OUT + col) = vA;
            *(float2*)(outB + (size_t)rowB * F_OUT + col) = vB;
        }
    }
}

extern "C" void kernel_launch(void* const* d_in, const int* in_sizes, int n_in,
                              void* d_out, int out_size)
{
    const float* h   = (const float*)d_in[0];   // (8,64,256,128)
    const float* W   = (const float*)d_in[1];   // (128,64)
    const float* a   = (const float*)d_in[2];   // (128,1)
    const float* adj = (const float*)d_in[3];   // (256,256)
    float* out = (float*)d_out;                 // (8,64,256,64)

    cudaFuncSetAttribute(gat_mma_kernel,
                         cudaFuncAttributeMaxDynamicSharedMemorySize, SM_TOTAL);
    gat_mma_kernel<<<BT_TOTAL, NTHR, SM_TOTAL>>>(h, W, a, adj, out);
}